// round 6
// baseline (speedup 1.0000x reference)
#include <cuda_runtime.h>
#include <cuda_bf16.h>
#include <cstdint>

typedef unsigned long long ull;

#define Bt   4
#define St   1024
#define HIDt 1024
#define NHt  16
#define HDt  64
#define LOG2E 1.4426950408889634f
#define NELEM (Bt * NHt * St * HDt)
#define XN (Bt * St * HIDt)
#define WN (HIDt * HIDt)

// bf16 hi/lo split scratch for Q (pre-scaled by 0.125), K, V in [B,NH,S,HD]
__device__ __nv_bfloat16 g_qh[NELEM], g_ql[NELEM];
__device__ __nv_bfloat16 g_kh[NELEM], g_kl[NELEM];
__device__ __nv_bfloat16 g_vh[NELEM], g_vl[NELEM];
// pre-split inputs: X and the 3 weight matrices (bf16 hi/lo)
__device__ __nv_bfloat16 g_xh[XN], g_xl[XN];
__device__ __nv_bfloat16 g_wh[3 * WN], g_wl[3 * WN];

// ---------------- helpers ----------------
__device__ __forceinline__ uint32_t cvta_s(const void* p) {
    return (uint32_t)__cvta_generic_to_shared(p);
}
__device__ __forceinline__ void ldsm4(uint32_t* r, uint32_t a) {
    asm volatile("ldmatrix.sync.aligned.m8n8.x4.shared.b16 {%0,%1,%2,%3},[%4];"
        : "=r"(r[0]), "=r"(r[1]), "=r"(r[2]), "=r"(r[3]) : "r"(a));
}
__device__ __forceinline__ void ldsm4t(uint32_t* r, uint32_t a) {
    asm volatile("ldmatrix.sync.aligned.m8n8.x4.trans.shared.b16 {%0,%1,%2,%3},[%4];"
        : "=r"(r[0]), "=r"(r[1]), "=r"(r[2]), "=r"(r[3]) : "r"(a));
}
__device__ __forceinline__ void mma_bf(float* c, const uint32_t* a, const uint32_t* b) {
    asm volatile("mma.sync.aligned.m16n8k16.row.col.f32.bf16.bf16.f32 "
        "{%0,%1,%2,%3},{%4,%5,%6,%7},{%8,%9},{%0,%1,%2,%3};"
        : "+f"(c[0]), "+f"(c[1]), "+f"(c[2]), "+f"(c[3])
        : "r"(a[0]), "r"(a[1]), "r"(a[2]), "r"(a[3]), "r"(b[0]), "r"(b[1]));
}
// pack two floats to bf16x2; e0 -> low half
__device__ __forceinline__ uint32_t pbf2(float e0, float e1) {
    uint32_t r; asm("cvt.rn.bf16x2.f32 %0, %1, %2;" : "=r"(r) : "f"(e1), "f"(e0)); return r;
}
__device__ __forceinline__ void splitf(float x, float& h, float& l) {
    h = __bfloat162float(__float2bfloat16(x));
    l = x - h;
}
__device__ __forceinline__ float ex2(float x) {
    float y; asm("ex2.approx.ftz.f32 %0, %1;" : "=f"(y) : "f"(x)); return y;
}

// ================= prep: split X / Wq / Wk / Wv to bf16 hi/lo ==============
__global__ __launch_bounds__(256)
void split_prep(const float* __restrict__ X,
                const float* __restrict__ Wq,
                const float* __restrict__ Wk,
                const float* __restrict__ Wv)
{
    const size_t idx = ((size_t)blockIdx.x * 256 + threadIdx.x) * 4;
    const float* src;
    __nv_bfloat16 *dh, *dl;
    size_t off;
    if (idx < XN)               { src = X;  dh = g_xh; dl = g_xl; off = idx; }
    else if (idx < XN + WN)     { src = Wq; dh = g_wh; dl = g_wl; off = idx - XN; }
    else if (idx < XN + 2 * WN) { src = Wk; dh = g_wh + WN; dl = g_wl + WN; off = idx - XN - WN; }
    else                        { src = Wv; dh = g_wh + 2 * WN; dl = g_wl + 2 * WN; off = idx - XN - 2 * WN; }
    const float4 v = *(const float4*)(src + off);
    float h0, l0, h1, l1, h2, l2, h3, l3;
    splitf(v.x, h0, l0); splitf(v.y, h1, l1);
    splitf(v.z, h2, l2); splitf(v.w, h3, l3);
    *(uint2*)(dh + off) = make_uint2(pbf2(h0, h1), pbf2(h2, h3));
    *(uint2*)(dl + off) = make_uint2(pbf2(l0, l1), pbf2(l2, l3));
}

// ================= QKV projection GEMM (pre-split, double-buffered) ========
// block tile 128(M) x 128(N), K-step 32, 2-stage smem; 8 warps: 4(M) x 2(N).
// Each array = 2 stages x 128 rows x 40 cols = 10240 bf16 entries.
#define QK_SMEM (4 * 10240 * 2)   // 81920 bytes
#define AHX(s,r,c) smA[(((s) * 128) + (r)) * 40 + (c)]
#define ALX(s,r,c) smA[10240 + (((s) * 128) + (r)) * 40 + (c)]
#define BHX(s,r,c) smA[20480 + (((s) * 128) + (r)) * 40 + (c)]
#define BLX(s,r,c) smA[30720 + (((s) * 128) + (r)) * 40 + (c)]

__global__ __launch_bounds__(256)
void qkv_gemm(const float* __restrict__ bq,
              const float* __restrict__ bk,
              const float* __restrict__ bv)
{
    extern __shared__ __align__(16) __nv_bfloat16 smA[];

    const int tid = threadIdx.x;
    const int bx = blockIdx.x, by = blockIdx.y, mz = blockIdx.z;
    const float* bias = (mz == 0) ? bq : (mz == 1) ? bk : bv;
    __nv_bfloat16* dh = (mz == 0) ? g_qh : (mz == 1) ? g_kh : g_vh;
    __nv_bfloat16* dl = (mz == 0) ? g_ql : (mz == 1) ? g_kl : g_vl;

    const int lr = tid >> 1;              // row 0..127
    const int lc = (tid & 1) * 16;        // bf16 col 0 / 16
    const int wid = tid >> 5, lane = tid & 31;
    const int wm = (wid & 3) * 32;
    const int wn = (wid >> 2) * 64;

    const __nv_bfloat16* Axh = g_xh + (size_t)(by * 128 + lr) * HIDt + lc;
    const __nv_bfloat16* Axl = g_xl + (size_t)(by * 128 + lr) * HIDt + lc;
    const __nv_bfloat16* Bwh = g_wh + (size_t)mz * WN + (size_t)(bx * 128 + lr) * HIDt + lc;
    const __nv_bfloat16* Bwl = g_wl + (size_t)mz * WN + (size_t)(bx * 128 + lr) * HIDt + lc;

    float acc[2][8][4];
#pragma unroll
    for (int i = 0; i < 2; ++i)
#pragma unroll
        for (int j = 0; j < 8; ++j)
#pragma unroll
            for (int k = 0; k < 4; ++k) acc[i][j][k] = 0.f;

    uint4 pah[2], pal[2], pbh[2], pbl[2];
#pragma unroll
    for (int c = 0; c < 2; ++c) {
        pah[c] = *(const uint4*)(Axh + c * 8);
        pal[c] = *(const uint4*)(Axl + c * 8);
        pbh[c] = *(const uint4*)(Bwh + c * 8);
        pbl[c] = *(const uint4*)(Bwl + c * 8);
    }
#pragma unroll
    for (int c = 0; c < 2; ++c) {
        *(uint4*)&AHX(0, lr, lc + c * 8) = pah[c];
        *(uint4*)&ALX(0, lr, lc + c * 8) = pal[c];
        *(uint4*)&BHX(0, lr, lc + c * 8) = pbh[c];
        *(uint4*)&BLX(0, lr, lc + c * 8) = pbl[c];
    }
    __syncthreads();

    for (int kt = 0; kt < 32; ++kt) {
        const int cur = kt & 1;
        if (kt + 1 < 32) {
            const int k0 = (kt + 1) * 32;
#pragma unroll
            for (int c = 0; c < 2; ++c) {
                pah[c] = *(const uint4*)(Axh + k0 + c * 8);
                pal[c] = *(const uint4*)(Axl + k0 + c * 8);
                pbh[c] = *(const uint4*)(Bwh + k0 + c * 8);
                pbl[c] = *(const uint4*)(Bwl + k0 + c * 8);
            }
        }
#pragma unroll
        for (int kb = 0; kb < 2; ++kb) {
            const int acol = kb * 16 + (lane >> 4) * 8;
            uint32_t a_h[2][4], a_l[2][4];
#pragma unroll
            for (int mi = 0; mi < 2; ++mi) {
                const int arow = wm + mi * 16 + (lane & 15);
                ldsm4(a_h[mi], cvta_s(&AHX(cur, arow, acol)));
                ldsm4(a_l[mi], cvta_s(&ALX(cur, arow, acol)));
            }
#pragma unroll
            for (int nb = 0; nb < 4; ++nb) {
                const int brow = wn + nb * 16 + (lane & 15);
                uint32_t bh4[4], bl4[4];
                ldsm4(bh4, cvta_s(&BHX(cur, brow, acol)));
                ldsm4(bl4, cvta_s(&BLX(cur, brow, acol)));
                uint32_t b0h[2] = {bh4[0], bh4[2]}, b1h[2] = {bh4[1], bh4[3]};
                uint32_t b0l[2] = {bl4[0], bl4[2]}, b1l[2] = {bl4[1], bl4[3]};
#pragma unroll
                for (int mi = 0; mi < 2; ++mi) {
                    float* c0 = acc[mi][nb * 2];
                    float* c1 = acc[mi][nb * 2 + 1];
                    mma_bf(c0, a_h[mi], b0h); mma_bf(c0, a_l[mi], b0h); mma_bf(c0, a_h[mi], b0l);
                    mma_bf(c1, a_h[mi], b1h); mma_bf(c1, a_l[mi], b1h); mma_bf(c1, a_h[mi], b1l);
                }
            }
        }
        if (kt + 1 < 32) {
            const int nxt = cur ^ 1;
#pragma unroll
            for (int c = 0; c < 2; ++c) {
                *(uint4*)&AHX(nxt, lr, lc + c * 8) = pah[c];
                *(uint4*)&ALX(nxt, lr, lc + c * 8) = pal[c];
                *(uint4*)&BHX(nxt, lr, lc + c * 8) = pbh[c];
                *(uint4*)&BLX(nxt, lr, lc + c * 8) = pbl[c];
            }
        }
        __syncthreads();
    }

    // epilogue: add bias, (0.125 scale for Q), split to bf16 hi/lo, scatter [B,NH,S,HD]
    const float qs = (mz == 0) ? 0.125f : 1.0f;
#pragma unroll
    for (int mi = 0; mi < 2; ++mi) {
#pragma unroll
        for (int nb2 = 0; nb2 < 8; ++nb2) {
            const int n = bx * 128 + wn + nb2 * 8 + (lane & 3) * 2;
            const float2 bv2 = *(const float2*)(bias + n);
            const int hh = n >> 6, d = n & 63;
#pragma unroll
            for (int rr = 0; rr < 2; ++rr) {
                const int m = by * 128 + wm + mi * 16 + (lane >> 2) + rr * 8;
                const int b = m >> 10, s = m & 1023;
                const float x0 = (acc[mi][nb2][rr * 2 + 0] + bv2.x) * qs;
                const float x1 = (acc[mi][nb2][rr * 2 + 1] + bv2.y) * qs;
                float h0, l0, h1, l1;
                splitf(x0, h0, l0); splitf(x1, h1, l1);
                const size_t off = (((size_t)(b * NHt + hh)) * St + s) * HDt + d;
                *(uint32_t*)&dh[off] = pbf2(h0, h1);
                *(uint32_t*)&dl[off] = pbf2(l0, l1);
            }
        }
    }
}

// ================= Flash attention (bf16-split mma, FA2 layout) =============
#define ASMEM (6 * 64 * 72 * 2 + 256)

__global__ __launch_bounds__(128)
void attn_mma(const float* __restrict__ mask, float* __restrict__ out)
{
    extern __shared__ __align__(16) char sm[];
    __nv_bfloat16 (*Qh)[72] = (__nv_bfloat16(*)[72])(sm);
    __nv_bfloat16 (*Ql)[72] = (__nv_bfloat16(*)[72])(sm + 9216);
    __nv_bfloat16 (*Kh)[72] = (__nv_bfloat16(*)[72])(sm + 18432);
    __nv_bfloat16 (*Kl)[72] = (__nv_bfloat16(*)[72])(sm + 27648);
    __nv_bfloat16 (*Vh)[72] = (__nv_bfloat16(*)[72])(sm + 36864);
    __nv_bfloat16 (*Vl)[72] = (__nv_bfloat16(*)[72])(sm + 46080);
    float* mb = (float*)(sm + 55296);

    const int tid = threadIdx.x;
    const int lane = tid & 31, wid = tid >> 5;
    const int qt = blockIdx.x, h = blockIdx.y, b = blockIdx.z;

    const size_t bh = ((size_t)(b * NHt + h)) * St * HDt;
    const __nv_bfloat16* qhp = g_qh + bh + (size_t)qt * 64 * HDt;
    const __nv_bfloat16* qlp = g_ql + bh + (size_t)qt * 64 * HDt;
    const __nv_bfloat16* khp = g_kh + bh;
    const __nv_bfloat16* klp = g_kl + bh;
    const __nv_bfloat16* vhp = g_vh + bh;
    const __nv_bfloat16* vlp = g_vl + bh;
    const float* mrow = mask + (size_t)b * St;

    for (int i = tid; i < 512; i += 128) {
        const int r = i >> 3, c = (i & 7) * 8;
        *(uint4*)&Qh[r][c] = *(const uint4*)(qhp + r * 64 + c);
        *(uint4*)&Ql[r][c] = *(const uint4*)(qlp + r * 64 + c);
    }

    float o[8][4];
#pragma unroll
    for (int j = 0; j < 8; ++j)
#pragma unroll
        for (int k = 0; k < 4; ++k) o[j][k] = 0.f;
    float m0 = -1e30f, m1 = -1e30f, l0 = 0.f, l1 = 0.f;

    for (int kt = 0; kt < 16; ++kt) {
        __syncthreads();
        const size_t ko = (size_t)kt * 64 * HDt;
        for (int i = tid; i < 512; i += 128) {
            const int r = i >> 3, c = (i & 7) * 8;
            *(uint4*)&Kh[r][c] = *(const uint4*)(khp + ko + r * 64 + c);
            *(uint4*)&Kl[r][c] = *(const uint4*)(klp + ko + r * 64 + c);
            *(uint4*)&Vh[r][c] = *(const uint4*)(vhp + ko + r * 64 + c);
            *(uint4*)&Vl[r][c] = *(const uint4*)(vlp + ko + r * 64 + c);
        }
        if (tid < 64) mb[tid] = (mrow[kt * 64 + tid] - 2.0f) * 1.0e6f;
        __syncthreads();

        float s[8][4];
#pragma unroll
        for (int j = 0; j < 8; ++j)
#pragma unroll
            for (int k = 0; k < 4; ++k) s[j][k] = 0.f;

#pragma unroll
        for (int kb = 0; kb < 4; ++kb) {
            uint32_t aqh[4], aql[4];
            const int qrow = wid * 16 + (lane & 15);
            const int qcol = kb * 16 + (lane >> 4) * 8;
            ldsm4(aqh, cvta_s(&Qh[qrow][qcol]));
            ldsm4(aql, cvta_s(&Ql[qrow][qcol]));
#pragma unroll
            for (int nb = 0; nb < 4; ++nb) {
                const int krow = nb * 16 + (lane & 15);
                uint32_t bh4[4], bl4[4];
                ldsm4(bh4, cvta_s(&Kh[krow][qcol]));
                ldsm4(bl4, cvta_s(&Kl[krow][qcol]));
                uint32_t b0h[2] = {bh4[0], bh4[2]}, b1h[2] = {bh4[1], bh4[3]};
                uint32_t b0l[2] = {bl4[0], bl4[2]}, b1l[2] = {bl4[1], bl4[3]};
                float* s0 = s[nb * 2];
                float* s1 = s[nb * 2 + 1];
                mma_bf(s0, aqh, b0h); mma_bf(s0, aql, b0h);
                mma_bf(s0, aqh, b0l); mma_bf(s0, aql, b0l);
                mma_bf(s1, aqh, b1h); mma_bf(s1, aql, b1h);
                mma_bf(s1, aqh, b1l); mma_bf(s1, aql, b1l);
            }
        }

        float rmax0 = -1e30f, rmax1 = -1e30f;
#pragma unroll
        for (int j = 0; j < 8; ++j) {
            const float bm0 = mb[j * 8 + (lane & 3) * 2];
            const float bm1 = mb[j * 8 + (lane & 3) * 2 + 1];
            s[j][0] += bm0; s[j][1] += bm1; s[j][2] += bm0; s[j][3] += bm1;
            rmax0 = fmaxf(rmax0, fmaxf(s[j][0], s[j][1]));
            rmax1 = fmaxf(rmax1, fmaxf(s[j][2], s[j][3]));
        }
        rmax0 = fmaxf(rmax0, __shfl_xor_sync(0xffffffffu, rmax0, 1));
        rmax0 = fmaxf(rmax0, __shfl_xor_sync(0xffffffffu, rmax0, 2));
        rmax1 = fmaxf(rmax1, __shfl_xor_sync(0xffffffffu, rmax1, 1));
        rmax1 = fmaxf(rmax1, __shfl_xor_sync(0xffffffffu, rmax1, 2));
        const float mn0 = fmaxf(m0, rmax0), mn1 = fmaxf(m1, rmax1);
        const float c0 = ex2((m0 - mn0) * LOG2E), c1 = ex2((m1 - mn1) * LOG2E);
        float rs0 = 0.f, rs1 = 0.f;

        uint32_t pah[4][4], pal[4][4];
#pragma unroll
        for (int j2 = 0; j2 < 4; ++j2) {
#pragma unroll
            for (int q = 0; q < 2; ++q) {
                const int j = j2 * 2 + q;
                const float p0 = ex2((s[j][0] - mn0) * LOG2E);
                const float p1 = ex2((s[j][1] - mn0) * LOG2E);
                const float p2 = ex2((s[j][2] - mn1) * LOG2E);
                const float p3 = ex2((s[j][3] - mn1) * LOG2E);
                rs0 += p0 + p1; rs1 += p2 + p3;
                float h0, e0, h1, e1, h2, e2, h3, e3;
                splitf(p0, h0, e0); splitf(p1, h1, e1);
                splitf(p2, h2, e2); splitf(p3, h3, e3);
                pah[j2][q * 2 + 0] = pbf2(h0, h1);
                pah[j2][q * 2 + 1] = pbf2(h2, h3);
                pal[j2][q * 2 + 0] = pbf2(e0, e1);
                pal[j2][q * 2 + 1] = pbf2(e2, e3);
            }
        }

        rs0 += __shfl_xor_sync(0xffffffffu, rs0, 1);
        rs0 += __shfl_xor_sync(0xffffffffu, rs0, 2);
        rs1 += __shfl_xor_sync(0xffffffffu, rs1, 1);
        rs1 += __shfl_xor_sync(0xffffffffu, rs1, 2);
        l0 = l0 * c0 + rs0; l1 = l1 * c1 + rs1;
        m0 = mn0; m1 = mn1;
#pragma unroll
        for (int j = 0; j < 8; ++j) {
            o[j][0] *= c0; o[j][1] *= c0; o[j][2] *= c1; o[j][3] *= c1;
        }

        const int grp = lane >> 3, li = lane & 7;
#pragma unroll
        for (int j2 = 0; j2 < 4; ++j2) {
            const int vr = j2 * 16 + ((grp & 1) ? 8 : 0) + li;
#pragma unroll
            for (int db = 0; db < 4; ++db) {
                const int vc = db * 16 + ((grp >= 2) ? 8 : 0);
                uint32_t vh4[4], vl4[4];
                ldsm4t(vh4, cvta_s(&Vh[vr][vc]));
                ldsm4t(vl4, cvta_s(&Vl[vr][vc]));
                uint32_t b0h[2] = {vh4[0], vh4[1]}, b1h[2] = {vh4[2], vh4[3]};
                uint32_t b0l[2] = {vl4[0], vl4[1]}, b1l[2] = {vl4[2], vl4[3]};
                float* o0 = o[db * 2];
                float* o1 = o[db * 2 + 1];
                mma_bf(o0, pah[j2], b0h); mma_bf(o0, pal[j2], b0h); mma_bf(o0, pah[j2], b0l);
                mma_bf(o1, pah[j2], b1h); mma_bf(o1, pal[j2], b1h); mma_bf(o1, pah[j2], b1l);
            }
        }
    }

    const float inv0 = 1.f / l0, inv1 = 1.f / l1;
    const int r0 = qt * 64 + wid * 16 + (lane >> 2);
#pragma unroll
    for (int db2 = 0; db2 < 8; ++db2) {
        const int d = db2 * 8 + (lane & 3) * 2;
        float2 v0 = make_float2(o[db2][0] * inv0, o[db2][1] * inv0);
        float2 v1 = make_float2(o[db2][2] * inv1, o[db2][3] * inv1);
        *(float2*)(out + (size_t)(b * St + r0) * HIDt + h * 64 + d) = v0;
        *(float2*)(out + (size_t)(b * St + r0 + 8) * HIDt + h * 64 + d) = v1;
    }
}

extern "C" void kernel_launch(void* const* d_in, const int* in_sizes, int n_in,
                              void* d_out, int out_size)
{
    const float* X    = (const float*)d_in[0];
    const float* mask = (const float*)d_in[1];
    const float* Wq   = (const float*)d_in[2];
    const float* bq   = (const float*)d_in[3];
    const float* Wk   = (const float*)d_in[4];
    const float* bk   = (const float*)d_in[5];
    const float* Wv   = (const float*)d_in[6];
    const float* bv   = (const float*)d_in[7];
    float* out = (float*)d_out;

    cudaFuncSetAttribute(qkv_gemm, cudaFuncAttributeMaxDynamicSharedMemorySize, QK_SMEM);
    cudaFuncSetAttribute(attn_mma, cudaFuncAttributeMaxDynamicSharedMemorySize, ASMEM);

    const int total4 = (XN + 3 * WN) / 4;
    split_prep<<<total4 / 256, 256>>>(X, Wq, Wk, Wv);

    dim3 g1(HIDt / 128, (Bt * St) / 128, 3);
    qkv_gemm<<<g1, 256, QK_SMEM>>>(bq, bk, bv);

    dim3 g2(St / 64, NHt, Bt);
    attn_mma<<<g2, 128, ASMEM>>>(mask, out);
}

// round 8
// speedup vs baseline: 1.0817x; 1.0817x over previous
#include <cuda_runtime.h>
#include <cuda_bf16.h>
#include <cstdint>

typedef unsigned long long ull;

#define Bt   4
#define St   1024
#define HIDt 1024
#define NHt  16
#define HDt  64
#define LOG2E 1.4426950408889634f
#define NELEM (Bt * NHt * St * HDt)
#define XN (Bt * St * HIDt)
#define WN (HIDt * HIDt)

__device__ __nv_bfloat16 g_qh[NELEM], g_ql[NELEM];
__device__ __nv_bfloat16 g_kh[NELEM], g_kl[NELEM];
__device__ __nv_bfloat16 g_vh[NELEM], g_vl[NELEM];
__device__ __nv_bfloat16 g_xh[XN], g_xl[XN];
__device__ __nv_bfloat16 g_wh[3 * WN], g_wl[3 * WN];

// ---------------- helpers ----------------
__device__ __forceinline__ uint32_t cvta_s(const void* p) {
    return (uint32_t)__cvta_generic_to_shared(p);
}
__device__ __forceinline__ void ldsm4(uint32_t* r, uint32_t a) {
    asm volatile("ldmatrix.sync.aligned.m8n8.x4.shared.b16 {%0,%1,%2,%3},[%4];"
        : "=r"(r[0]), "=r"(r[1]), "=r"(r[2]), "=r"(r[3]) : "r"(a));
}
__device__ __forceinline__ void ldsm4t(uint32_t* r, uint32_t a) {
    asm volatile("ldmatrix.sync.aligned.m8n8.x4.trans.shared.b16 {%0,%1,%2,%3},[%4];"
        : "=r"(r[0]), "=r"(r[1]), "=r"(r[2]), "=r"(r[3]) : "r"(a));
}
__device__ __forceinline__ void mma_bf(float* c, const uint32_t* a, const uint32_t* b) {
    asm volatile("mma.sync.aligned.m16n8k16.row.col.f32.bf16.bf16.f32 "
        "{%0,%1,%2,%3},{%4,%5,%6,%7},{%8,%9},{%0,%1,%2,%3};"
        : "+f"(c[0]), "+f"(c[1]), "+f"(c[2]), "+f"(c[3])
        : "r"(a[0]), "r"(a[1]), "r"(a[2]), "r"(a[3]), "r"(b[0]), "r"(b[1]));
}
__device__ __forceinline__ uint32_t pbf2(float e0, float e1) {
    uint32_t r; asm("cvt.rn.bf16x2.f32 %0, %1, %2;" : "=r"(r) : "f"(e1), "f"(e0)); return r;
}
__device__ __forceinline__ void splitf(float x, float& h, float& l) {
    h = __bfloat162float(__float2bfloat16(x));
    l = x - h;
}
__device__ __forceinline__ float ex2(float x) {
    float y; asm("ex2.approx.ftz.f32 %0, %1;" : "=f"(y) : "f"(x)); return y;
}
__device__ __forceinline__ void cpa16(uint32_t dst, const void* src) {
    asm volatile("cp.async.cg.shared.global [%0], [%1], 16;" :: "r"(dst), "l"(src));
}
__device__ __forceinline__ void cp_commit() { asm volatile("cp.async.commit_group;"); }
template<int N> __device__ __forceinline__ void cp_wait() {
    asm volatile("cp.async.wait_group %0;" :: "n"(N));
}

// ================= prep: split X / Wq / Wk / Wv to bf16 hi/lo ==============
__global__ __launch_bounds__(256)
void split_prep(const float* __restrict__ X,
                const float* __restrict__ Wq,
                const float* __restrict__ Wk,
                const float* __restrict__ Wv)
{
    const size_t idx = ((size_t)blockIdx.x * 256 + threadIdx.x) * 4;
    const float* src;
    __nv_bfloat16 *dh, *dl;
    size_t off;
    if (idx < XN)               { src = X;  dh = g_xh; dl = g_xl; off = idx; }
    else if (idx < XN + WN)     { src = Wq; dh = g_wh; dl = g_wl; off = idx - XN; }
    else if (idx < XN + 2 * WN) { src = Wk; dh = g_wh + WN; dl = g_wl + WN; off = idx - XN - WN; }
    else                        { src = Wv; dh = g_wh + 2 * WN; dl = g_wl + 2 * WN; off = idx - XN - 2 * WN; }
    const float4 v = *(const float4*)(src + off);
    float h0, l0, h1, l1, h2, l2, h3, l3;
    splitf(v.x, h0, l0); splitf(v.y, h1, l1);
    splitf(v.z, h2, l2); splitf(v.w, h3, l3);
    *(uint2*)(dh + off) = make_uint2(pbf2(h0, h1), pbf2(h2, h3));
    *(uint2*)(dl + off) = make_uint2(pbf2(l0, l1), pbf2(l2, l3));
}

// ======== QKV GEMM: cp.async 3-stage, XOR-swizzled, coalesced epilogue ======
// CTA tile 128x128, K slabs of 32 (32 slabs). 8 warps: 4(M) x 2(N).
// smem: 4 arrays (AH,AL,BH,BL) x 3 stages x 8192 B = 98304 B.
// Rows are 64B (32 K x bf16); 16B chunk c stored at position c ^ ((row>>1)&3).
#define QS_STG 8192
#define S_AH 0
#define S_AL 24576
#define S_BH 49152
#define S_BL 73728
#define QK_SMEM 98304

__global__ __launch_bounds__(256, 2)
void qkv_gemm(const float* __restrict__ bq,
              const float* __restrict__ bk,
              const float* __restrict__ bv)
{
    extern __shared__ __align__(16) char smq[];
    const uint32_t sb = cvta_s(smq);

    const int tid = threadIdx.x;
    const int wid = tid >> 5, lane = tid & 31;
    const int bx = blockIdx.x, by = blockIdx.y, mz = blockIdx.z;
    const float* bias = (mz == 0) ? bq : (mz == 1) ? bk : bv;
    __nv_bfloat16* dh = (mz == 0) ? g_qh : (mz == 1) ? g_kh : g_vh;
    __nv_bfloat16* dl = (mz == 0) ? g_ql : (mz == 1) ? g_kl : g_vl;

    const int wm = (wid & 3) * 32;
    const int wn = (wid >> 2) * 64;

    // loader: row r (0..127), chunk pair ch (0 or 2)
    const int r = tid >> 1;
    const int ch = (tid & 1) * 2;
    const __nv_bfloat16* Axh = g_xh + (size_t)(by * 128 + r) * HIDt;
    const __nv_bfloat16* Axl = g_xl + (size_t)(by * 128 + r) * HIDt;
    const __nv_bfloat16* Bwh = g_wh + (size_t)mz * WN + (size_t)(bx * 128 + r) * HIDt;
    const __nv_bfloat16* Bwl = g_wl + (size_t)mz * WN + (size_t)(bx * 128 + r) * HIDt;
    const uint32_t swr = (uint32_t)r * 64;
    const uint32_t xs = (r >> 1) & 3;
    const uint32_t sw0 = swr + (((ch + 0) ^ xs) << 4);
    const uint32_t sw1 = swr + (((ch + 1) ^ xs) << 4);

#define QISSUE(slab, st) do {                                            \
        const int k0_ = (slab) * 32 + ch * 8;                            \
        const uint32_t o0_ = (st) * QS_STG + sw0;                        \
        const uint32_t o1_ = (st) * QS_STG + sw1;                        \
        cpa16(sb + S_AH + o0_, Axh + k0_); cpa16(sb + S_AH + o1_, Axh + k0_ + 8); \
        cpa16(sb + S_AL + o0_, Axl + k0_); cpa16(sb + S_AL + o1_, Axl + k0_ + 8); \
        cpa16(sb + S_BH + o0_, Bwh + k0_); cpa16(sb + S_BH + o1_, Bwh + k0_ + 8); \
        cpa16(sb + S_BL + o0_, Bwl + k0_); cpa16(sb + S_BL + o1_, Bwl + k0_ + 8); \
        cp_commit();                                                     \
    } while (0)

    float acc[2][8][4];
#pragma unroll
    for (int i = 0; i < 2; ++i)
#pragma unroll
        for (int j = 0; j < 8; ++j)
#pragma unroll
            for (int k = 0; k < 4; ++k) acc[i][j][k] = 0.f;

    // per-warp ldsm address precompute
    uint32_t abase_r[2], xa[2];
#pragma unroll
    for (int mi = 0; mi < 2; ++mi) {
        const int arow = wm + mi * 16 + (lane & 15);
        abase_r[mi] = (uint32_t)arow * 64;
        xa[mi] = (arow >> 1) & 3;
    }
    uint32_t bbase_r[4], xb[4];
#pragma unroll
    for (int nb = 0; nb < 4; ++nb) {
        const int brow = wn + nb * 16 + (lane & 15);
        bbase_r[nb] = (uint32_t)brow * 64;
        xb[nb] = (brow >> 1) & 3;
    }
    const int chalf = lane >> 4;   // k-chunk half selector for ldsm

    QISSUE(0, 0);
    QISSUE(1, 1);

    for (int s = 0; s < 32; ++s) {
        const int st = s % 3;
        if (s < 31) cp_wait<1>(); else cp_wait<0>();
        __syncthreads();
        if (s + 2 < 32) QISSUE(s + 2, (s + 2) % 3);

        const uint32_t ah = sb + S_AH + st * QS_STG;
        const uint32_t al = sb + S_AL + st * QS_STG;
        const uint32_t bh = sb + S_BH + st * QS_STG;
        const uint32_t bl = sb + S_BL + st * QS_STG;
#pragma unroll
        for (int kb = 0; kb < 2; ++kb) {
            const uint32_t ccol = kb * 2 + chalf;
            uint32_t a_h[2][4], a_l[2][4];
#pragma unroll
            for (int mi = 0; mi < 2; ++mi) {
                const uint32_t aoff = abase_r[mi] + ((ccol ^ xa[mi]) << 4);
                ldsm4(a_h[mi], ah + aoff);
                ldsm4(a_l[mi], al + aoff);
            }
#pragma unroll
            for (int nb = 0; nb < 4; ++nb) {
                const uint32_t boff = bbase_r[nb] + ((ccol ^ xb[nb]) << 4);
                uint32_t bh4[4], bl4[4];
                ldsm4(bh4, bh + boff);
                ldsm4(bl4, bl + boff);
                uint32_t b0h[2] = {bh4[0], bh4[2]}, b1h[2] = {bh4[1], bh4[3]};
                uint32_t b0l[2] = {bl4[0], bl4[2]}, b1l[2] = {bl4[1], bl4[3]};
#pragma unroll
                for (int mi = 0; mi < 2; ++mi) {
                    float* c0 = acc[mi][nb * 2];
                    float* c1 = acc[mi][nb * 2 + 1];
                    mma_bf(c0, a_h[mi], b0h); mma_bf(c0, a_l[mi], b0h); mma_bf(c0, a_h[mi], b0l);
                    mma_bf(c1, a_h[mi], b1h); mma_bf(c1, a_l[mi], b1h); mma_bf(c1, a_h[mi], b1l);
                }
            }
        }
    }
    __syncthreads();

    // ---- epilogue: frags -> smem (Ch/Cl, stride 68 uint32) -> coalesced gmem
    uint32_t* Ch = (uint32_t*)smq;             // 128*68*4 = 34816 B
    uint32_t* Cl = (uint32_t*)(smq + 34816);   // total 69632 <= 98304
    const float qs = (mz == 0) ? 0.125f : 1.0f;
#pragma unroll
    for (int mi = 0; mi < 2; ++mi) {
#pragma unroll
        for (int nb2 = 0; nb2 < 8; ++nb2) {
            const int n = bx * 128 + wn + nb2 * 8 + (lane & 3) * 2;
            const float2 bv2 = *(const float2*)(bias + n);
            const int colu = (wn >> 1) + nb2 * 4 + (lane & 3);
#pragma unroll
            for (int rr = 0; rr < 2; ++rr) {
                const int row = wm + mi * 16 + (lane >> 2) + rr * 8;
                const float x0 = (acc[mi][nb2][rr * 2 + 0] + bv2.x) * qs;
                const float x1 = (acc[mi][nb2][rr * 2 + 1] + bv2.y) * qs;
                float h0, l0, h1, l1;
                splitf(x0, h0, l0); splitf(x1, h1, l1);
                Ch[row * 68 + colu] = pbf2(h0, h1);
                Cl[row * 68 + colu] = pbf2(l0, l1);
            }
        }
    }
    __syncthreads();

    // copyout: 4096 uint4 segments; consecutive tid -> consecutive gmem 16B
#pragma unroll
    for (int it = 0; it < 16; ++it) {
        const int idx = tid + it * 256;
        const int a = idx >> 11;           // 0 = hi, 1 = lo
        const int rem = idx & 2047;
        const int j = rem & 7;
        const int row = (rem >> 3) & 127;
        const int half = (rem >> 10) & 1;
        const uint32_t sbyte = (uint32_t)a * 34816 + (uint32_t)row * 272 + half * 128 + j * 16;
        const uint4 v = *(const uint4*)(smq + sbyte);
        const int m = by * 128 + row;
        const int bsel = m >> 10, sq = m & 1023;
        const int head = bx * 2 + half;
        const size_t off = (((size_t)(bsel * NHt + head)) * St + sq) * HDt + j * 8;
        *(uint4*)((a ? dl : dh) + off) = v;
    }
#undef QISSUE
}

// ================= Flash attention (bf16-split mma, FA2 layout) =============
#define ASMEM (6 * 64 * 72 * 2 + 256)

__global__ __launch_bounds__(128)
void attn_mma(const float* __restrict__ mask, float* __restrict__ out)
{
    extern __shared__ __align__(16) char sma[];
    __nv_bfloat16 (*Qh)[72] = (__nv_bfloat16(*)[72])(sma);
    __nv_bfloat16 (*Ql)[72] = (__nv_bfloat16(*)[72])(sma + 9216);
    __nv_bfloat16 (*Kh)[72] = (__nv_bfloat16(*)[72])(sma + 18432);
    __nv_bfloat16 (*Kl)[72] = (__nv_bfloat16(*)[72])(sma + 27648);
    __nv_bfloat16 (*Vh)[72] = (__nv_bfloat16(*)[72])(sma + 36864);
    __nv_bfloat16 (*Vl)[72] = (__nv_bfloat16(*)[72])(sma + 46080);
    float* mb = (float*)(sma + 55296);

    const int tid = threadIdx.x;
    const int lane = tid & 31, wid = tid >> 5;
    const int qt = blockIdx.x, h = blockIdx.y, b = blockIdx.z;

    const size_t bh = ((size_t)(b * NHt + h)) * St * HDt;
    const __nv_bfloat16* qhp = g_qh + bh + (size_t)qt * 64 * HDt;
    const __nv_bfloat16* qlp = g_ql + bh + (size_t)qt * 64 * HDt;
    const __nv_bfloat16* khp = g_kh + bh;
    const __nv_bfloat16* klp = g_kl + bh;
    const __nv_bfloat16* vhp = g_vh + bh;
    const __nv_bfloat16* vlp = g_vl + bh;
    const float* mrow = mask + (size_t)b * St;

    for (int i = tid; i < 512; i += 128) {
        const int r = i >> 3, c = (i & 7) * 8;
        *(uint4*)&Qh[r][c] = *(const uint4*)(qhp + r * 64 + c);
        *(uint4*)&Ql[r][c] = *(const uint4*)(qlp + r * 64 + c);
    }

    float o[8][4];
#pragma unroll
    for (int j = 0; j < 8; ++j)
#pragma unroll
        for (int k = 0; k < 4; ++k) o[j][k] = 0.f;
    float m0 = -1e30f, m1 = -1e30f, l0 = 0.f, l1 = 0.f;

    for (int kt = 0; kt < 16; ++kt) {
        __syncthreads();
        const size_t ko = (size_t)kt * 64 * HDt;
        for (int i = tid; i < 512; i += 128) {
            const int r = i >> 3, c = (i & 7) * 8;
            *(uint4*)&Kh[r][c] = *(const uint4*)(khp + ko + r * 64 + c);
            *(uint4*)&Kl[r][c] = *(const uint4*)(klp + ko + r * 64 + c);
            *(uint4*)&Vh[r][c] = *(const uint4*)(vhp + ko + r * 64 + c);
            *(uint4*)&Vl[r][c] = *(const uint4*)(vlp + ko + r * 64 + c);
        }
        if (tid < 64) mb[tid] = (mrow[kt * 64 + tid] - 2.0f) * 1.0e6f;
        __syncthreads();

        float s[8][4];
#pragma unroll
        for (int j = 0; j < 8; ++j)
#pragma unroll
            for (int k = 0; k < 4; ++k) s[j][k] = 0.f;

#pragma unroll
        for (int kb = 0; kb < 4; ++kb) {
            uint32_t aqh[4], aql[4];
            const int qrow = wid * 16 + (lane & 15);
            const int qcol = kb * 16 + (lane >> 4) * 8;
            ldsm4(aqh, cvta_s(&Qh[qrow][qcol]));
            ldsm4(aql, cvta_s(&Ql[qrow][qcol]));
#pragma unroll
            for (int nb = 0; nb < 4; ++nb) {
                const int krow = nb * 16 + (lane & 15);
                uint32_t bh4[4], bl4[4];
                ldsm4(bh4, cvta_s(&Kh[krow][qcol]));
                ldsm4(bl4, cvta_s(&Kl[krow][qcol]));
                uint32_t b0h[2] = {bh4[0], bh4[2]}, b1h[2] = {bh4[1], bh4[3]};
                uint32_t b0l[2] = {bl4[0], bl4[2]}, b1l[2] = {bl4[1], bl4[3]};
                float* s0 = s[nb * 2];
                float* s1 = s[nb * 2 + 1];
                mma_bf(s0, aqh, b0h); mma_bf(s0, aql, b0h);
                mma_bf(s0, aqh, b0l); mma_bf(s0, aql, b0l);
                mma_bf(s1, aqh, b1h); mma_bf(s1, aql, b1h);
                mma_bf(s1, aqh, b1l); mma_bf(s1, aql, b1l);
            }
        }

        float rmax0 = -1e30f, rmax1 = -1e30f;
#pragma unroll
        for (int j = 0; j < 8; ++j) {
            const float bm0 = mb[j * 8 + (lane & 3) * 2];
            const float bm1 = mb[j * 8 + (lane & 3) * 2 + 1];
            s[j][0] += bm0; s[j][1] += bm1; s[j][2] += bm0; s[j][3] += bm1;
            rmax0 = fmaxf(rmax0, fmaxf(s[j][0], s[j][1]));
            rmax1 = fmaxf(rmax1, fmaxf(s[j][2], s[j][3]));
        }
        rmax0 = fmaxf(rmax0, __shfl_xor_sync(0xffffffffu, rmax0, 1));
        rmax0 = fmaxf(rmax0, __shfl_xor_sync(0xffffffffu, rmax0, 2));
        rmax1 = fmaxf(rmax1, __shfl_xor_sync(0xffffffffu, rmax1, 1));
        rmax1 = fmaxf(rmax1, __shfl_xor_sync(0xffffffffu, rmax1, 2));
        const float mn0 = fmaxf(m0, rmax0), mn1 = fmaxf(m1, rmax1);
        const float c0 = ex2((m0 - mn0) * LOG2E), c1 = ex2((m1 - mn1) * LOG2E);
        float rs0 = 0.f, rs1 = 0.f;

        uint32_t pah[4][4], pal[4][4];
#pragma unroll
        for (int j2 = 0; j2 < 4; ++j2) {
#pragma unroll
            for (int q = 0; q < 2; ++q) {
                const int j = j2 * 2 + q;
                const float p0 = ex2((s[j][0] - mn0) * LOG2E);
                const float p1 = ex2((s[j][1] - mn0) * LOG2E);
                const float p2 = ex2((s[j][2] - mn1) * LOG2E);
                const float p3 = ex2((s[j][3] - mn1) * LOG2E);
                rs0 += p0 + p1; rs1 += p2 + p3;
                float h0, e0, h1, e1, h2, e2, h3, e3;
                splitf(p0, h0, e0); splitf(p1, h1, e1);
                splitf(p2, h2, e2); splitf(p3, h3, e3);
                pah[j2][q * 2 + 0] = pbf2(h0, h1);
                pah[j2][q * 2 + 1] = pbf2(h2, h3);
                pal[j2][q * 2 + 0] = pbf2(e0, e1);
                pal[j2][q * 2 + 1] = pbf2(e2, e3);
            }
        }

        rs0 += __shfl_xor_sync(0xffffffffu, rs0, 1);
        rs0 += __shfl_xor_sync(0xffffffffu, rs0, 2);
        rs1 += __shfl_xor_sync(0xffffffffu, rs1, 1);
        rs1 += __shfl_xor_sync(0xffffffffu, rs1, 2);
        l0 = l0 * c0 + rs0; l1 = l1 * c1 + rs1;
        m0 = mn0; m1 = mn1;
#pragma unroll
        for (int j = 0; j < 8; ++j) {
            o[j][0] *= c0; o[j][1] *= c0; o[j][2] *= c1; o[j][3] *= c1;
        }

        const int grp = lane >> 3, li = lane & 7;
#pragma unroll
        for (int j2 = 0; j2 < 4; ++j2) {
            const int vr = j2 * 16 + ((grp & 1) ? 8 : 0) + li;
#pragma unroll
            for (int db = 0; db < 4; ++db) {
                const int vc = db * 16 + ((grp >= 2) ? 8 : 0);
                uint32_t vh4[4], vl4[4];
                ldsm4t(vh4, cvta_s(&Vh[vr][vc]));
                ldsm4t(vl4, cvta_s(&Vl[vr][vc]));
                uint32_t b0h[2] = {vh4[0], vh4[1]}, b1h[2] = {vh4[2], vh4[3]};
                uint32_t b0l[2] = {vl4[0], vl4[1]}, b1l[2] = {vl4[2], vl4[3]};
                float* o0 = o[db * 2];
                float* o1 = o[db * 2 + 1];
                mma_bf(o0, pah[j2], b0h); mma_bf(o0, pal[j2], b0h); mma_bf(o0, pah[j2], b0l);
                mma_bf(o1, pah[j2], b1h); mma_bf(o1, pal[j2], b1h); mma_bf(o1, pah[j2], b1l);
            }
        }
    }

    const float inv0 = 1.f / l0, inv1 = 1.f / l1;
    const int r0 = qt * 64 + wid * 16 + (lane >> 2);
#pragma unroll
    for (int db2 = 0; db2 < 8; ++db2) {
        const int d = db2 * 8 + (lane & 3) * 2;
        float2 v0 = make_float2(o[db2][0] * inv0, o[db2][1] * inv0);
        float2 v1 = make_float2(o[db2][2] * inv1, o[db2][3] * inv1);
        *(float2*)(out + (size_t)(b * St + r0) * HIDt + h * 64 + d) = v0;
        *(float2*)(out + (size_t)(b * St + r0 + 8) * HIDt + h * 64 + d) = v1;
    }
}

extern "C" void kernel_launch(void* const* d_in, const int* in_sizes, int n_in,
                              void* d_out, int out_size)
{
    const float* X    = (const float*)d_in[0];
    const float* mask = (const float*)d_in[1];
    const float* Wq   = (const float*)d_in[2];
    const float* bq   = (const float*)d_in[3];
    const float* Wk   = (const float*)d_in[4];
    const float* bk   = (const float*)d_in[5];
    const float* Wv   = (const float*)d_in[6];
    const float* bv   = (const float*)d_in[7];
    float* out = (float*)d_out;

    cudaFuncSetAttribute(qkv_gemm, cudaFuncAttributeMaxDynamicSharedMemorySize, QK_SMEM);
    cudaFuncSetAttribute(attn_mma, cudaFuncAttributeMaxDynamicSharedMemorySize, ASMEM);

    const int total4 = (XN + 3 * WN) / 4;
    split_prep<<<total4 / 256, 256>>>(X, Wq, Wk, Wv);

    dim3 g1(HIDt / 128, (Bt * St) / 128, 3);
    qkv_gemm<<<g1, 256, QK_SMEM>>>(bq, bk, bv);

    dim3 g2(St / 64, NHt, Bt);
    attn_mma<<<g2, 128, ASMEM>>>(mask, out);
}

// round 9
// speedup vs baseline: 1.3047x; 1.2062x over previous
#include <cuda_runtime.h>
#include <cuda_fp16.h>
#include <cstdint>

typedef unsigned long long ull;

#define Bt   4
#define St   1024
#define HIDt 1024
#define NHt  16
#define HDt  64
#define LOG2E 1.4426950408889634f
#define NELEM (Bt * NHt * St * HDt)
#define XN (Bt * St * HIDt)
#define WN (HIDt * HIDt)

// fp16 hi/lo split scratch. Q pre-scaled by 0.125. V stored single-fp16 (hi only).
__device__ __half g_qh[NELEM], g_ql[NELEM];
__device__ __half g_kh[NELEM], g_kl[NELEM];
__device__ __half g_vh[NELEM];
__device__ __half g_xh[XN], g_xl[XN];
__device__ __half g_wh[3 * WN], g_wl[3 * WN];

// ---------------- helpers ----------------
__device__ __forceinline__ uint32_t cvta_s(const void* p) {
    return (uint32_t)__cvta_generic_to_shared(p);
}
__device__ __forceinline__ void ldsm4(uint32_t* r, uint32_t a) {
    asm volatile("ldmatrix.sync.aligned.m8n8.x4.shared.b16 {%0,%1,%2,%3},[%4];"
        : "=r"(r[0]), "=r"(r[1]), "=r"(r[2]), "=r"(r[3]) : "r"(a));
}
__device__ __forceinline__ void ldsm4t(uint32_t* r, uint32_t a) {
    asm volatile("ldmatrix.sync.aligned.m8n8.x4.trans.shared.b16 {%0,%1,%2,%3},[%4];"
        : "=r"(r[0]), "=r"(r[1]), "=r"(r[2]), "=r"(r[3]) : "r"(a));
}
__device__ __forceinline__ void mma_hf(float* c, const uint32_t* a, const uint32_t* b) {
    asm volatile("mma.sync.aligned.m16n8k16.row.col.f32.f16.f16.f32 "
        "{%0,%1,%2,%3},{%4,%5,%6,%7},{%8,%9},{%0,%1,%2,%3};"
        : "+f"(c[0]), "+f"(c[1]), "+f"(c[2]), "+f"(c[3])
        : "r"(a[0]), "r"(a[1]), "r"(a[2]), "r"(a[3]), "r"(b[0]), "r"(b[1]));
}
// pack two floats to f16x2; e0 -> low half
__device__ __forceinline__ uint32_t phf2(float e0, float e1) {
    uint32_t r; asm("cvt.rn.f16x2.f32 %0, %1, %2;" : "=r"(r) : "f"(e1), "f"(e0)); return r;
}
__device__ __forceinline__ void splith(float x, float& h, float& l) {
    h = __half2float(__float2half(x));
    l = x - h;
}
__device__ __forceinline__ float ex2(float x) {
    float y; asm("ex2.approx.ftz.f32 %0, %1;" : "=f"(y) : "f"(x)); return y;
}
__device__ __forceinline__ void cpa16(uint32_t dst, const void* src) {
    asm volatile("cp.async.cg.shared.global [%0], [%1], 16;" :: "r"(dst), "l"(src));
}
__device__ __forceinline__ void cp_commit() { asm volatile("cp.async.commit_group;"); }
template<int N> __device__ __forceinline__ void cp_wait() {
    asm volatile("cp.async.wait_group %0;" :: "n"(N));
}

// ================= prep: split X / Wq / Wk / Wv to fp16 hi/lo ==============
__global__ __launch_bounds__(256)
void split_prep(const float* __restrict__ X,
                const float* __restrict__ Wq,
                const float* __restrict__ Wk,
                const float* __restrict__ Wv)
{
    const size_t idx = ((size_t)blockIdx.x * 256 + threadIdx.x) * 4;
    const float* src;
    __half *dh, *dl;
    size_t off;
    if (idx < XN)               { src = X;  dh = g_xh; dl = g_xl; off = idx; }
    else if (idx < XN + WN)     { src = Wq; dh = g_wh; dl = g_wl; off = idx - XN; }
    else if (idx < XN + 2 * WN) { src = Wk; dh = g_wh + WN; dl = g_wl + WN; off = idx - XN - WN; }
    else                        { src = Wv; dh = g_wh + 2 * WN; dl = g_wl + 2 * WN; off = idx - XN - 2 * WN; }
    const float4 v = *(const float4*)(src + off);
    float h0, l0, h1, l1, h2, l2, h3, l3;
    splith(v.x, h0, l0); splith(v.y, h1, l1);
    splith(v.z, h2, l2); splith(v.w, h3, l3);
    *(uint2*)(dh + off) = make_uint2(phf2(h0, h1), phf2(h2, h3));
    *(uint2*)(dl + off) = make_uint2(phf2(l0, l1), phf2(l2, l3));
}

// ======== QKV GEMM: cp.async 3-stage, XOR-swizzled, coalesced epilogue ======
// CTA 128x128, K slabs of 32. Q/K: 3-term fp16 split; V: 2-term (W single).
#define QS_STG 8192
#define S_AH 0
#define S_AL 24576
#define S_BH 49152
#define S_BL 73728
#define QK_SMEM 98304

__global__ __launch_bounds__(256, 2)
void qkv_gemm(const float* __restrict__ bq,
              const float* __restrict__ bk,
              const float* __restrict__ bv)
{
    extern __shared__ __align__(16) char smq[];
    const uint32_t sb = cvta_s(smq);

    const int tid = threadIdx.x;
    const int wid = tid >> 5, lane = tid & 31;
    const int bx = blockIdx.x, by = blockIdx.y, mz = blockIdx.z;
    const float* bias = (mz == 0) ? bq : (mz == 1) ? bk : bv;
    __half* dh = (mz == 0) ? g_qh : (mz == 1) ? g_kh : g_vh;
    __half* dl = (mz == 0) ? g_ql : (mz == 1) ? g_kl : g_qh /*unused for V*/;
    const bool full3 = (mz != 2);

    const int wm = (wid & 3) * 32;
    const int wn = (wid >> 2) * 64;

    const int r = tid >> 1;
    const int ch = (tid & 1) * 2;
    const __half* Axh = g_xh + (size_t)(by * 128 + r) * HIDt;
    const __half* Axl = g_xl + (size_t)(by * 128 + r) * HIDt;
    const __half* Bwh = g_wh + (size_t)mz * WN + (size_t)(bx * 128 + r) * HIDt;
    const __half* Bwl = g_wl + (size_t)mz * WN + (size_t)(bx * 128 + r) * HIDt;
    const uint32_t swr = (uint32_t)r * 64;
    const uint32_t xs = (r >> 1) & 3;
    const uint32_t sw0 = swr + (((ch + 0) ^ xs) << 4);
    const uint32_t sw1 = swr + (((ch + 1) ^ xs) << 4);

#define QISSUE(slab, st) do {                                            \
        const int k0_ = (slab) * 32 + ch * 8;                            \
        const uint32_t o0_ = (st) * QS_STG + sw0;                        \
        const uint32_t o1_ = (st) * QS_STG + sw1;                        \
        cpa16(sb + S_AH + o0_, Axh + k0_); cpa16(sb + S_AH + o1_, Axh + k0_ + 8); \
        cpa16(sb + S_AL + o0_, Axl + k0_); cpa16(sb + S_AL + o1_, Axl + k0_ + 8); \
        cpa16(sb + S_BH + o0_, Bwh + k0_); cpa16(sb + S_BH + o1_, Bwh + k0_ + 8); \
        if (full3) { cpa16(sb + S_BL + o0_, Bwl + k0_); cpa16(sb + S_BL + o1_, Bwl + k0_ + 8); } \
        cp_commit();                                                     \
    } while (0)

    float acc[2][8][4];
#pragma unroll
    for (int i = 0; i < 2; ++i)
#pragma unroll
        for (int j = 0; j < 8; ++j)
#pragma unroll
            for (int k = 0; k < 4; ++k) acc[i][j][k] = 0.f;

    uint32_t abase_r[2], xa[2];
#pragma unroll
    for (int mi = 0; mi < 2; ++mi) {
        const int arow = wm + mi * 16 + (lane & 15);
        abase_r[mi] = (uint32_t)arow * 64;
        xa[mi] = (arow >> 1) & 3;
    }
    uint32_t bbase_r[4], xb[4];
#pragma unroll
    for (int nb = 0; nb < 4; ++nb) {
        const int brow = wn + nb * 16 + (lane & 15);
        bbase_r[nb] = (uint32_t)brow * 64;
        xb[nb] = (brow >> 1) & 3;
    }
    const int chalf = lane >> 4;

    QISSUE(0, 0);
    QISSUE(1, 1);

    for (int s = 0; s < 32; ++s) {
        const int st = s % 3;
        if (s < 31) cp_wait<1>(); else cp_wait<0>();
        __syncthreads();
        if (s + 2 < 32) QISSUE(s + 2, (s + 2) % 3);

        const uint32_t ah = sb + S_AH + st * QS_STG;
        const uint32_t al = sb + S_AL + st * QS_STG;
        const uint32_t bh = sb + S_BH + st * QS_STG;
        const uint32_t bl = sb + S_BL + st * QS_STG;
#pragma unroll
        for (int kb = 0; kb < 2; ++kb) {
            const uint32_t ccol = kb * 2 + chalf;
            uint32_t a_h[2][4], a_l[2][4];
#pragma unroll
            for (int mi = 0; mi < 2; ++mi) {
                const uint32_t aoff = abase_r[mi] + ((ccol ^ xa[mi]) << 4);
                ldsm4(a_h[mi], ah + aoff);
                ldsm4(a_l[mi], al + aoff);
            }
#pragma unroll
            for (int nb = 0; nb < 4; ++nb) {
                const uint32_t boff = bbase_r[nb] + ((ccol ^ xb[nb]) << 4);
                uint32_t bh4[4], bl4[4];
                ldsm4(bh4, bh + boff);
                if (full3) ldsm4(bl4, bl + boff);
                uint32_t b0h[2] = {bh4[0], bh4[2]}, b1h[2] = {bh4[1], bh4[3]};
#pragma unroll
                for (int mi = 0; mi < 2; ++mi) {
                    float* c0 = acc[mi][nb * 2];
                    float* c1 = acc[mi][nb * 2 + 1];
                    mma_hf(c0, a_h[mi], b0h); mma_hf(c0, a_l[mi], b0h);
                    mma_hf(c1, a_h[mi], b1h); mma_hf(c1, a_l[mi], b1h);
                    if (full3) {
                        uint32_t b0l[2] = {bl4[0], bl4[2]}, b1l[2] = {bl4[1], bl4[3]};
                        mma_hf(c0, a_h[mi], b0l);
                        mma_hf(c1, a_h[mi], b1l);
                    }
                }
            }
        }
    }
    __syncthreads();

    // ---- epilogue: frags -> smem (stride-68 uint32) -> coalesced gmem
    uint32_t* Ch = (uint32_t*)smq;
    uint32_t* Cl = (uint32_t*)(smq + 34816);
    const float qs = (mz == 0) ? 0.125f : 1.0f;
#pragma unroll
    for (int mi = 0; mi < 2; ++mi) {
#pragma unroll
        for (int nb2 = 0; nb2 < 8; ++nb2) {
            const int n = bx * 128 + wn + nb2 * 8 + (lane & 3) * 2;
            const float2 bv2 = *(const float2*)(bias + n);
            const int colu = (wn >> 1) + nb2 * 4 + (lane & 3);
#pragma unroll
            for (int rr = 0; rr < 2; ++rr) {
                const int row = wm + mi * 16 + (lane >> 2) + rr * 8;
                const float x0 = (acc[mi][nb2][rr * 2 + 0] + bv2.x) * qs;
                const float x1 = (acc[mi][nb2][rr * 2 + 1] + bv2.y) * qs;
                float h0, l0, h1, l1;
                splith(x0, h0, l0); splith(x1, h1, l1);
                Ch[row * 68 + colu] = phf2(h0, h1);
                Cl[row * 68 + colu] = phf2(l0, l1);
            }
        }
    }
    __syncthreads();

#pragma unroll
    for (int it = 0; it < 16; ++it) {
        const int idx = tid + it * 256;
        const int a = idx >> 11;
        if (a == 1 && !full3) continue;   // V has no lo plane
        const int rem = idx & 2047;
        const int j = rem & 7;
        const int row = (rem >> 3) & 127;
        const int half = (rem >> 10) & 1;
        const uint32_t sbyte = (uint32_t)a * 34816 + (uint32_t)row * 272 + half * 128 + j * 16;
        const uint4 v = *(const uint4*)(smq + sbyte);
        const int m = by * 128 + row;
        const int bsel = m >> 10, sq = m & 1023;
        const int head = bx * 2 + half;
        const size_t off = (((size_t)(bsel * NHt + head)) * St + sq) * HDt + j * 8;
        *(uint4*)((a ? dl : dh) + off) = v;
    }
#undef QISSUE
}

// ================= Flash attention (fp16: 3-term S, 1-term PV) =============
#define ASMEM (5 * 64 * 72 * 2 + 256)

__global__ __launch_bounds__(128)
void attn_mma(const float* __restrict__ mask, float* __restrict__ out)
{
    extern __shared__ __align__(16) char sma[];
    __half (*Qh)[72] = (__half(*)[72])(sma);
    __half (*Ql)[72] = (__half(*)[72])(sma + 9216);
    __half (*Kh)[72] = (__half(*)[72])(sma + 18432);
    __half (*Kl)[72] = (__half(*)[72])(sma + 27648);
    __half (*Vs)[72] = (__half(*)[72])(sma + 36864);
    float* mb = (float*)(sma + 46080);

    const int tid = threadIdx.x;
    const int lane = tid & 31, wid = tid >> 5;
    const int qt = blockIdx.x, h = blockIdx.y, b = blockIdx.z;

    const size_t bh = ((size_t)(b * NHt + h)) * St * HDt;
    const __half* qhp = g_qh + bh + (size_t)qt * 64 * HDt;
    const __half* qlp = g_ql + bh + (size_t)qt * 64 * HDt;
    const __half* khp = g_kh + bh;
    const __half* klp = g_kl + bh;
    const __half* vhp = g_vh + bh;
    const float* mrow = mask + (size_t)b * St;

    for (int i = tid; i < 512; i += 128) {
        const int r = i >> 3, c = (i & 7) * 8;
        *(uint4*)&Qh[r][c] = *(const uint4*)(qhp + r * 64 + c);
        *(uint4*)&Ql[r][c] = *(const uint4*)(qlp + r * 64 + c);
    }

    float o[8][4];
#pragma unroll
    for (int j = 0; j < 8; ++j)
#pragma unroll
        for (int k = 0; k < 4; ++k) o[j][k] = 0.f;
    float m0 = -1e30f, m1 = -1e30f, l0 = 0.f, l1 = 0.f;

    for (int kt = 0; kt < 16; ++kt) {
        __syncthreads();
        const size_t ko = (size_t)kt * 64 * HDt;
        for (int i = tid; i < 512; i += 128) {
            const int r = i >> 3, c = (i & 7) * 8;
            *(uint4*)&Kh[r][c] = *(const uint4*)(khp + ko + r * 64 + c);
            *(uint4*)&Kl[r][c] = *(const uint4*)(klp + ko + r * 64 + c);
            *(uint4*)&Vs[r][c] = *(const uint4*)(vhp + ko + r * 64 + c);
        }
        if (tid < 64) mb[tid] = (mrow[kt * 64 + tid] - 2.0f) * 1.0e6f;
        __syncthreads();

        float s[8][4];
#pragma unroll
        for (int j = 0; j < 8; ++j)
#pragma unroll
            for (int k = 0; k < 4; ++k) s[j][k] = 0.f;

#pragma unroll
        for (int kb = 0; kb < 4; ++kb) {
            uint32_t aqh[4], aql[4];
            const int qrow = wid * 16 + (lane & 15);
            const int qcol = kb * 16 + (lane >> 4) * 8;
            ldsm4(aqh, cvta_s(&Qh[qrow][qcol]));
            ldsm4(aql, cvta_s(&Ql[qrow][qcol]));
#pragma unroll
            for (int nb = 0; nb < 4; ++nb) {
                const int krow = nb * 16 + (lane & 15);
                uint32_t bh4[4], bl4[4];
                ldsm4(bh4, cvta_s(&Kh[krow][qcol]));
                ldsm4(bl4, cvta_s(&Kl[krow][qcol]));
                uint32_t b0h[2] = {bh4[0], bh4[2]}, b1h[2] = {bh4[1], bh4[3]};
                uint32_t b0l[2] = {bl4[0], bl4[2]}, b1l[2] = {bl4[1], bl4[3]};
                float* s0 = s[nb * 2];
                float* s1 = s[nb * 2 + 1];
                mma_hf(s0, aqh, b0h); mma_hf(s0, aql, b0h); mma_hf(s0, aqh, b0l);
                mma_hf(s1, aqh, b1h); mma_hf(s1, aql, b1h); mma_hf(s1, aqh, b1l);
            }
        }

        float rmax0 = -1e30f, rmax1 = -1e30f;
#pragma unroll
        for (int j = 0; j < 8; ++j) {
            const float bm0 = mb[j * 8 + (lane & 3) * 2];
            const float bm1 = mb[j * 8 + (lane & 3) * 2 + 1];
            s[j][0] += bm0; s[j][1] += bm1; s[j][2] += bm0; s[j][3] += bm1;
            rmax0 = fmaxf(rmax0, fmaxf(s[j][0], s[j][1]));
            rmax1 = fmaxf(rmax1, fmaxf(s[j][2], s[j][3]));
        }
        rmax0 = fmaxf(rmax0, __shfl_xor_sync(0xffffffffu, rmax0, 1));
        rmax0 = fmaxf(rmax0, __shfl_xor_sync(0xffffffffu, rmax0, 2));
        rmax1 = fmaxf(rmax1, __shfl_xor_sync(0xffffffffu, rmax1, 1));
        rmax1 = fmaxf(rmax1, __shfl_xor_sync(0xffffffffu, rmax1, 2));
        const float mn0 = fmaxf(m0, rmax0), mn1 = fmaxf(m1, rmax1);
        const float c0 = ex2((m0 - mn0) * LOG2E), c1 = ex2((m1 - mn1) * LOG2E);
        float rs0 = 0.f, rs1 = 0.f;

        uint32_t pa[4][4];
#pragma unroll
        for (int j2 = 0; j2 < 4; ++j2) {
#pragma unroll
            for (int q = 0; q < 2; ++q) {
                const int j = j2 * 2 + q;
                const float p0 = ex2((s[j][0] - mn0) * LOG2E);
                const float p1 = ex2((s[j][1] - mn0) * LOG2E);
                const float p2 = ex2((s[j][2] - mn1) * LOG2E);
                const float p3 = ex2((s[j][3] - mn1) * LOG2E);
                rs0 += p0 + p1; rs1 += p2 + p3;
                pa[j2][q * 2 + 0] = phf2(p0, p1);
                pa[j2][q * 2 + 1] = phf2(p2, p3);
            }
        }

        rs0 += __shfl_xor_sync(0xffffffffu, rs0, 1);
        rs0 += __shfl_xor_sync(0xffffffffu, rs0, 2);
        rs1 += __shfl_xor_sync(0xffffffffu, rs1, 1);
        rs1 += __shfl_xor_sync(0xffffffffu, rs1, 2);
        l0 = l0 * c0 + rs0; l1 = l1 * c1 + rs1;
        m0 = mn0; m1 = mn1;
#pragma unroll
        for (int j = 0; j < 8; ++j) {
            o[j][0] *= c0; o[j][1] *= c0; o[j][2] *= c1; o[j][3] *= c1;
        }

        const int grp = lane >> 3, li = lane & 7;
#pragma unroll
        for (int j2 = 0; j2 < 4; ++j2) {
            const int vr = j2 * 16 + ((grp & 1) ? 8 : 0) + li;
#pragma unroll
            for (int db = 0; db < 4; ++db) {
                const int vc = db * 16 + ((grp >= 2) ? 8 : 0);
                uint32_t vh4[4];
                ldsm4t(vh4, cvta_s(&Vs[vr][vc]));
                uint32_t b0h[2] = {vh4[0], vh4[1]}, b1h[2] = {vh4[2], vh4[3]};
                mma_hf(o[db * 2],     pa[j2], b0h);
                mma_hf(o[db * 2 + 1], pa[j2], b1h);
            }
        }
    }

    const float inv0 = 1.f / l0, inv1 = 1.f / l1;
    const int r0 = qt * 64 + wid * 16 + (lane >> 2);
#pragma unroll
    for (int db2 = 0; db2 < 8; ++db2) {
        const int d = db2 * 8 + (lane & 3) * 2;
        float2 v0 = make_float2(o[db2][0] * inv0, o[db2][1] * inv0);
        float2 v1 = make_float2(o[db2][2] * inv1, o[db2][3] * inv1);
        *(float2*)(out + (size_t)(b * St + r0) * HIDt + h * 64 + d) = v0;
        *(float2*)(out + (size_t)(b * St + r0 + 8) * HIDt + h * 64 + d) = v1;
    }
}

extern "C" void kernel_launch(void* const* d_in, const int* in_sizes, int n_in,
                              void* d_out, int out_size)
{
    const float* X    = (const float*)d_in[0];
    const float* mask = (const float*)d_in[1];
    const float* Wq   = (const float*)d_in[2];
    const float* bq   = (const float*)d_in[3];
    const float* Wk   = (const float*)d_in[4];
    const float* bk   = (const float*)d_in[5];
    const float* Wv   = (const float*)d_in[6];
    const float* bv   = (const float*)d_in[7];
    float* out = (float*)d_out;

    cudaFuncSetAttribute(qkv_gemm, cudaFuncAttributeMaxDynamicSharedMemorySize, QK_SMEM);
    cudaFuncSetAttribute(attn_mma, cudaFuncAttributeMaxDynamicSharedMemorySize, ASMEM);

    const int total4 = (XN + 3 * WN) / 4;
    split_prep<<<total4 / 256, 256>>>(X, Wq, Wk, Wv);

    dim3 g1(HIDt / 128, (Bt * St) / 128, 3);
    qkv_gemm<<<g1, 256, QK_SMEM>>>(bq, bk, bv);

    dim3 g2(St / 64, NHt, Bt);
    attn_mma<<<g2, 128, ASMEM>>>(mask, out);
}

// round 10
// speedup vs baseline: 1.4519x; 1.1128x over previous
#include <cuda_runtime.h>
#include <cuda_fp16.h>
#include <cstdint>

typedef unsigned long long ull;

#define Bt   4
#define St   1024
#define HIDt 1024
#define NHt  16
#define HDt  64
#define LOG2E 1.4426950408889634f
#define NELEM (Bt * NHt * St * HDt)
#define XN (Bt * St * HIDt)
#define WN (HIDt * HIDt)

// fp16 hi/lo split scratch. Q pre-scaled by 0.125. V stored single-fp16.
__device__ __half g_qh[NELEM], g_ql[NELEM];
__device__ __half g_kh[NELEM], g_kl[NELEM];
__device__ __half g_vh[NELEM];
__device__ __half g_xh[XN], g_xl[XN];
__device__ __half g_wh[3 * WN], g_wl[3 * WN];

// ---------------- helpers ----------------
__device__ __forceinline__ uint32_t cvta_s(const void* p) {
    return (uint32_t)__cvta_generic_to_shared(p);
}
__device__ __forceinline__ void ldsm4(uint32_t* r, uint32_t a) {
    asm volatile("ldmatrix.sync.aligned.m8n8.x4.shared.b16 {%0,%1,%2,%3},[%4];"
        : "=r"(r[0]), "=r"(r[1]), "=r"(r[2]), "=r"(r[3]) : "r"(a));
}
__device__ __forceinline__ void ldsm4t(uint32_t* r, uint32_t a) {
    asm volatile("ldmatrix.sync.aligned.m8n8.x4.trans.shared.b16 {%0,%1,%2,%3},[%4];"
        : "=r"(r[0]), "=r"(r[1]), "=r"(r[2]), "=r"(r[3]) : "r"(a));
}
__device__ __forceinline__ void mma_hf(float* c, const uint32_t* a, const uint32_t* b) {
    asm volatile("mma.sync.aligned.m16n8k16.row.col.f32.f16.f16.f32 "
        "{%0,%1,%2,%3},{%4,%5,%6,%7},{%8,%9},{%0,%1,%2,%3};"
        : "+f"(c[0]), "+f"(c[1]), "+f"(c[2]), "+f"(c[3])
        : "r"(a[0]), "r"(a[1]), "r"(a[2]), "r"(a[3]), "r"(b[0]), "r"(b[1]));
}
__device__ __forceinline__ uint32_t phf2(float e0, float e1) {
    uint32_t r; asm("cvt.rn.f16x2.f32 %0, %1, %2;" : "=r"(r) : "f"(e1), "f"(e0)); return r;
}
__device__ __forceinline__ void splith(float x, float& h, float& l) {
    h = __half2float(__float2half(x));
    l = x - h;
}
__device__ __forceinline__ float ex2(float x) {
    float y; asm("ex2.approx.ftz.f32 %0, %1;" : "=f"(y) : "f"(x)); return y;
}
__device__ __forceinline__ void cpa16(uint32_t dst, const void* src) {
    asm volatile("cp.async.cg.shared.global [%0], [%1], 16;" :: "r"(dst), "l"(src));
}
__device__ __forceinline__ void cp_commit() { asm volatile("cp.async.commit_group;"); }
template<int N> __device__ __forceinline__ void cp_wait() {
    asm volatile("cp.async.wait_group %0;" :: "n"(N));
}

// ================= prep: split X / Wq / Wk / Wv to fp16 hi/lo ==============
__global__ __launch_bounds__(256)
void split_prep(const float* __restrict__ X,
                const float* __restrict__ Wq,
                const float* __restrict__ Wk,
                const float* __restrict__ Wv)
{
    const size_t idx = ((size_t)blockIdx.x * 256 + threadIdx.x) * 4;
    const float* src;
    __half *dh, *dl;
    size_t off;
    if (idx < XN)               { src = X;  dh = g_xh; dl = g_xl; off = idx; }
    else if (idx < XN + WN)     { src = Wq; dh = g_wh; dl = g_wl; off = idx - XN; }
    else if (idx < XN + 2 * WN) { src = Wk; dh = g_wh + WN; dl = g_wl + WN; off = idx - XN - WN; }
    else                        { src = Wv; dh = g_wh + 2 * WN; dl = g_wl + 2 * WN; off = idx - XN - 2 * WN; }
    const float4 v = *(const float4*)(src + off);
    float h0, l0, h1, l1, h2, l2, h3, l3;
    splith(v.x, h0, l0); splith(v.y, h1, l1);
    splith(v.z, h2, l2); splith(v.w, h3, l3);
    *(uint2*)(dh + off) = make_uint2(phf2(h0, h1), phf2(h2, h3));
    *(uint2*)(dl + off) = make_uint2(phf2(l0, l1), phf2(l2, l3));
}

// ======== QK fused GEMM: tile 128(M) x 256(N = Q128|K128), 512 threads ======
// A (X, hi+lo) loaded ONCE per tile and shared by Q and K. 3-term fp16 split.
// smem: AH/AL 3x8KB each, BH/BL 3x16KB each = 144 KB. 1 CTA/SM, 16 warps.
#define QK_S_AH 0
#define QK_S_AL 24576
#define QK_S_BH 49152
#define QK_S_BL 98304
#define QK2_SMEM 147456

__global__ __launch_bounds__(512, 1)
void qk_gemm(const float* __restrict__ bq, const float* __restrict__ bk)
{
    extern __shared__ __align__(16) char smq[];
    const uint32_t sb = cvta_s(smq);

    const int tid = threadIdx.x;
    const int wid = tid >> 5, lane = tid & 31;
    const int bx = blockIdx.x, by = blockIdx.y;

    const int wm = (wid & 3) * 32;
    const int wn = (wid >> 2) * 64;   // 0,64 -> Q ; 128,192 -> K

    // A loader: row rA (0..127), chunk cA (0..3); one chunk for AH and AL
    const int rA = tid >> 2, cA = tid & 3;
    const __half* Axh = g_xh + (size_t)(by * 128 + rA) * HIDt;
    const __half* Axl = g_xl + (size_t)(by * 128 + rA) * HIDt;
    const uint32_t swA = (uint32_t)rA * 64 + (((uint32_t)cA ^ ((rA >> 1) & 3)) << 4);

    // B loader: row rB (0..255: 0-127 Wq, 128-255 Wk), chunk pair chp
    const int rB = tid >> 1, chp = (tid & 1) * 2;
    const size_t woff = (size_t)(rB >> 7) * WN + (size_t)(bx * 128 + (rB & 127)) * HIDt;
    const __half* Bwh = g_wh + woff;
    const __half* Bwl = g_wl + woff;
    const uint32_t xsB = (rB >> 1) & 3;
    const uint32_t swB0 = (uint32_t)rB * 64 + ((((uint32_t)chp + 0) ^ xsB) << 4);
    const uint32_t swB1 = (uint32_t)rB * 64 + ((((uint32_t)chp + 1) ^ xsB) << 4);

#define QKISSUE(slab, st) do {                                                  \
        const int k0_ = (slab) * 32;                                            \
        cpa16(sb + QK_S_AH + (st) * 8192 + swA, Axh + k0_ + cA * 8);            \
        cpa16(sb + QK_S_AL + (st) * 8192 + swA, Axl + k0_ + cA * 8);            \
        cpa16(sb + QK_S_BH + (st) * 16384 + swB0, Bwh + k0_ + chp * 8);         \
        cpa16(sb + QK_S_BH + (st) * 16384 + swB1, Bwh + k0_ + chp * 8 + 8);     \
        cpa16(sb + QK_S_BL + (st) * 16384 + swB0, Bwl + k0_ + chp * 8);         \
        cpa16(sb + QK_S_BL + (st) * 16384 + swB1, Bwl + k0_ + chp * 8 + 8);     \
        cp_commit();                                                            \
    } while (0)

    float acc[2][8][4];
#pragma unroll
    for (int i = 0; i < 2; ++i)
#pragma unroll
        for (int j = 0; j < 8; ++j)
#pragma unroll
            for (int k = 0; k < 4; ++k) acc[i][j][k] = 0.f;

    uint32_t abase_r[2], xa[2];
#pragma unroll
    for (int mi = 0; mi < 2; ++mi) {
        const int arow = wm + mi * 16 + (lane & 15);
        abase_r[mi] = (uint32_t)arow * 64;
        xa[mi] = (arow >> 1) & 3;
    }
    uint32_t bbase_r[4], xb[4];
#pragma unroll
    for (int nb = 0; nb < 4; ++nb) {
        const int brow = wn + nb * 16 + (lane & 15);   // 0..255
        bbase_r[nb] = (uint32_t)brow * 64;
        xb[nb] = (brow >> 1) & 3;
    }
    const int chalf = lane >> 4;

    QKISSUE(0, 0);
    QKISSUE(1, 1);

    for (int s = 0; s < 32; ++s) {
        const int st = s % 3;
        if (s < 31) cp_wait<1>(); else cp_wait<0>();
        __syncthreads();
        if (s + 2 < 32) QKISSUE(s + 2, (s + 2) % 3);

        const uint32_t ah = sb + QK_S_AH + st * 8192;
        const uint32_t al = sb + QK_S_AL + st * 8192;
        const uint32_t bh = sb + QK_S_BH + st * 16384;
        const uint32_t bl = sb + QK_S_BL + st * 16384;
#pragma unroll
        for (int kb = 0; kb < 2; ++kb) {
            const uint32_t ccol = kb * 2 + chalf;
            uint32_t a_h[2][4], a_l[2][4];
#pragma unroll
            for (int mi = 0; mi < 2; ++mi) {
                const uint32_t aoff = abase_r[mi] + ((ccol ^ xa[mi]) << 4);
                ldsm4(a_h[mi], ah + aoff);
                ldsm4(a_l[mi], al + aoff);
            }
#pragma unroll
            for (int nb = 0; nb < 4; ++nb) {
                const uint32_t boff = bbase_r[nb] + ((ccol ^ xb[nb]) << 4);
                uint32_t bh4[4], bl4[4];
                ldsm4(bh4, bh + boff);
                ldsm4(bl4, bl + boff);
                uint32_t b0h[2] = {bh4[0], bh4[2]}, b1h[2] = {bh4[1], bh4[3]};
                uint32_t b0l[2] = {bl4[0], bl4[2]}, b1l[2] = {bl4[1], bl4[3]};
#pragma unroll
                for (int mi = 0; mi < 2; ++mi) {
                    float* c0 = acc[mi][nb * 2];
                    float* c1 = acc[mi][nb * 2 + 1];
                    mma_hf(c0, a_h[mi], b0h); mma_hf(c0, a_l[mi], b0h); mma_hf(c0, a_h[mi], b0l);
                    mma_hf(c1, a_h[mi], b1h); mma_hf(c1, a_l[mi], b1h); mma_hf(c1, a_h[mi], b1l);
                }
            }
        }
    }
    __syncthreads();

    // ---- epilogue: frags -> smem (stride 132 u32) -> coalesced gmem
    uint32_t* Cp = (uint32_t*)smq;    // [2 planes][128 rows][132 u32]; 2*67584 B
    const float* bias = (wn < 128) ? bq : bk;
    const float qs = (wn < 128) ? 0.125f : 1.0f;
#pragma unroll
    for (int mi = 0; mi < 2; ++mi) {
#pragma unroll
        for (int nb2 = 0; nb2 < 8; ++nb2) {
            const int ncol = wn + nb2 * 8 + (lane & 3) * 2;          // 0..255
            const float2 bv2 = *(const float2*)(bias + bx * 128 + (ncol & 127));
            const int colu = ncol >> 1;                               // 0..127
#pragma unroll
            for (int rr = 0; rr < 2; ++rr) {
                const int row = wm + mi * 16 + (lane >> 2) + rr * 8;
                const float x0 = (acc[mi][nb2][rr * 2 + 0] + bv2.x) * qs;
                const float x1 = (acc[mi][nb2][rr * 2 + 1] + bv2.y) * qs;
                float h0, l0, h1, l1;
                splith(x0, h0, l0); splith(x1, h1, l1);
                Cp[row * 132 + colu]             = phf2(h0, h1);
                Cp[16896 + row * 132 + colu]     = phf2(l0, l1);
            }
        }
    }
    __syncthreads();

    // copyout: 8192 uint4; consecutive tid -> consecutive gmem 16B
#pragma unroll
    for (int it = 0; it < 16; ++it) {
        const int idx = tid + it * 512;
        const int a = idx >> 12;              // 0=hi, 1=lo
        const int rem = idx & 4095;
        const int row = rem >> 5;
        const int j = rem & 31;               // uint4 within row (n = j*8)
        const uint32_t sbyte = (uint32_t)a * 67584 + (uint32_t)row * 528 + j * 16;
        const uint4 v = *(const uint4*)(smq + sbyte);
        const int n = j * 8;
        const int ncol = n & 127;
        __half* dst = (n < 128) ? (a ? g_ql : g_qh) : (a ? g_kl : g_kh);
        const int m = by * 128 + row;
        const int bsel = m >> 10, sq = m & 1023;
        const int head = bx * 2 + (ncol >> 6);
        const size_t off = (((size_t)(bsel * NHt + head)) * St + sq) * HDt + (ncol & 63);
        *(uint4*)(dst + off) = v;
    }
#undef QKISSUE
}

// ======== V GEMM: 1-term fp16 (x_h * w_h), tile 128x128, 256 threads =======
#define V_S_AH 0
#define V_S_BH 24576
#define V_SMEM 49152

__global__ __launch_bounds__(256, 2)
void v_gemm(const float* __restrict__ bv)
{
    extern __shared__ __align__(16) char smv[];
    const uint32_t sb = cvta_s(smv);

    const int tid = threadIdx.x;
    const int wid = tid >> 5, lane = tid & 31;
    const int bx = blockIdx.x, by = blockIdx.y;

    const int wm = (wid & 3) * 32;
    const int wn = (wid >> 2) * 64;

    const int r = tid >> 1;
    const int ch = (tid & 1) * 2;
    const __half* Axh = g_xh + (size_t)(by * 128 + r) * HIDt;
    const __half* Bwh = g_wh + 2 * (size_t)WN + (size_t)(bx * 128 + r) * HIDt;
    const uint32_t xs = (r >> 1) & 3;
    const uint32_t sw0 = (uint32_t)r * 64 + ((((uint32_t)ch + 0) ^ xs) << 4);
    const uint32_t sw1 = (uint32_t)r * 64 + ((((uint32_t)ch + 1) ^ xs) << 4);

#define VISSUE(slab, st) do {                                            \
        const int k0_ = (slab) * 32 + ch * 8;                            \
        cpa16(sb + V_S_AH + (st) * 8192 + sw0, Axh + k0_);               \
        cpa16(sb + V_S_AH + (st) * 8192 + sw1, Axh + k0_ + 8);           \
        cpa16(sb + V_S_BH + (st) * 8192 + sw0, Bwh + k0_);               \
        cpa16(sb + V_S_BH + (st) * 8192 + sw1, Bwh + k0_ + 8);           \
        cp_commit();                                                     \
    } while (0)

    float acc[2][8][4];
#pragma unroll
    for (int i = 0; i < 2; ++i)
#pragma unroll
        for (int j = 0; j < 8; ++j)
#pragma unroll
            for (int k = 0; k < 4; ++k) acc[i][j][k] = 0.f;

    uint32_t abase_r[2], xa[2];
#pragma unroll
    for (int mi = 0; mi < 2; ++mi) {
        const int arow = wm + mi * 16 + (lane & 15);
        abase_r[mi] = (uint32_t)arow * 64;
        xa[mi] = (arow >> 1) & 3;
    }
    uint32_t bbase_r[4], xb[4];
#pragma unroll
    for (int nb = 0; nb < 4; ++nb) {
        const int brow = wn + nb * 16 + (lane & 15);
        bbase_r[nb] = (uint32_t)brow * 64;
        xb[nb] = (brow >> 1) & 3;
    }
    const int chalf = lane >> 4;

    VISSUE(0, 0);
    VISSUE(1, 1);

    for (int s = 0; s < 32; ++s) {
        const int st = s % 3;
        if (s < 31) cp_wait<1>(); else cp_wait<0>();
        __syncthreads();
        if (s + 2 < 32) VISSUE(s + 2, (s + 2) % 3);

        const uint32_t ah = sb + V_S_AH + st * 8192;
        const uint32_t bh = sb + V_S_BH + st * 8192;
#pragma unroll
        for (int kb = 0; kb < 2; ++kb) {
            const uint32_t ccol = kb * 2 + chalf;
            uint32_t a_h[2][4];
#pragma unroll
            for (int mi = 0; mi < 2; ++mi) {
                const uint32_t aoff = abase_r[mi] + ((ccol ^ xa[mi]) << 4);
                ldsm4(a_h[mi], ah + aoff);
            }
#pragma unroll
            for (int nb = 0; nb < 4; ++nb) {
                const uint32_t boff = bbase_r[nb] + ((ccol ^ xb[nb]) << 4);
                uint32_t bh4[4];
                ldsm4(bh4, bh + boff);
                uint32_t b0h[2] = {bh4[0], bh4[2]}, b1h[2] = {bh4[1], bh4[3]};
#pragma unroll
                for (int mi = 0; mi < 2; ++mi) {
                    mma_hf(acc[mi][nb * 2],     a_h[mi], b0h);
                    mma_hf(acc[mi][nb * 2 + 1], a_h[mi], b1h);
                }
            }
        }
    }
    __syncthreads();

    // epilogue (hi plane only)
    uint32_t* Ch = (uint32_t*)smv;   // [128][68]
#pragma unroll
    for (int mi = 0; mi < 2; ++mi) {
#pragma unroll
        for (int nb2 = 0; nb2 < 8; ++nb2) {
            const int n = bx * 128 + wn + nb2 * 8 + (lane & 3) * 2;
            const float2 bv2 = *(const float2*)(bv + n);
            const int colu = (wn >> 1) + nb2 * 4 + (lane & 3);
#pragma unroll
            for (int rr = 0; rr < 2; ++rr) {
                const int row = wm + mi * 16 + (lane >> 2) + rr * 8;
                const float x0 = acc[mi][nb2][rr * 2 + 0] + bv2.x;
                const float x1 = acc[mi][nb2][rr * 2 + 1] + bv2.y;
                Ch[row * 68 + colu] = phf2(x0, x1);
            }
        }
    }
    __syncthreads();

#pragma unroll
    for (int it = 0; it < 8; ++it) {
        const int idx = tid + it * 256;       // 2048 uint4
        const int j = idx & 7;
        const int row = (idx >> 3) & 127;
        const int half = (idx >> 10) & 1;
        const uint32_t sbyte = (uint32_t)row * 272 + half * 128 + j * 16;
        const uint4 v = *(const uint4*)(smv + sbyte);
        const int m = by * 128 + row;
        const int bsel = m >> 10, sq = m & 1023;
        const int head = bx * 2 + half;
        const size_t off = (((size_t)(bsel * NHt + head)) * St + sq) * HDt + j * 8;
        *(uint4*)(g_vh + off) = v;
    }
#undef VISSUE
}

// ================= Flash attention (fp16: 3-term S, 1-term PV) =============
#define ASMEM (5 * 64 * 72 * 2 + 256)

__global__ __launch_bounds__(128)
void attn_mma(const float* __restrict__ mask, float* __restrict__ out)
{
    extern __shared__ __align__(16) char sma[];
    __half (*Qh)[72] = (__half(*)[72])(sma);
    __half (*Ql)[72] = (__half(*)[72])(sma + 9216);
    __half (*Kh)[72] = (__half(*)[72])(sma + 18432);
    __half (*Kl)[72] = (__half(*)[72])(sma + 27648);
    __half (*Vs)[72] = (__half(*)[72])(sma + 36864);
    float* mb = (float*)(sma + 46080);

    const int tid = threadIdx.x;
    const int lane = tid & 31, wid = tid >> 5;
    const int qt = blockIdx.x, h = blockIdx.y, b = blockIdx.z;

    const size_t bh = ((size_t)(b * NHt + h)) * St * HDt;
    const __half* qhp = g_qh + bh + (size_t)qt * 64 * HDt;
    const __half* qlp = g_ql + bh + (size_t)qt * 64 * HDt;
    const __half* khp = g_kh + bh;
    const __half* klp = g_kl + bh;
    const __half* vhp = g_vh + bh;
    const float* mrow = mask + (size_t)b * St;

    for (int i = tid; i < 512; i += 128) {
        const int r = i >> 3, c = (i & 7) * 8;
        *(uint4*)&Qh[r][c] = *(const uint4*)(qhp + r * 64 + c);
        *(uint4*)&Ql[r][c] = *(const uint4*)(qlp + r * 64 + c);
    }

    float o[8][4];
#pragma unroll
    for (int j = 0; j < 8; ++j)
#pragma unroll
        for (int k = 0; k < 4; ++k) o[j][k] = 0.f;
    float m0 = -1e30f, m1 = -1e30f, l0 = 0.f, l1 = 0.f;

    for (int kt = 0; kt < 16; ++kt) {
        __syncthreads();
        const size_t ko = (size_t)kt * 64 * HDt;
        for (int i = tid; i < 512; i += 128) {
            const int r = i >> 3, c = (i & 7) * 8;
            *(uint4*)&Kh[r][c] = *(const uint4*)(khp + ko + r * 64 + c);
            *(uint4*)&Kl[r][c] = *(const uint4*)(klp + ko + r * 64 + c);
            *(uint4*)&Vs[r][c] = *(const uint4*)(vhp + ko + r * 64 + c);
        }
        if (tid < 64) mb[tid] = (mrow[kt * 64 + tid] - 2.0f) * 1.0e6f;
        __syncthreads();

        float s[8][4];
#pragma unroll
        for (int j = 0; j < 8; ++j)
#pragma unroll
            for (int k = 0; k < 4; ++k) s[j][k] = 0.f;

#pragma unroll
        for (int kb = 0; kb < 4; ++kb) {
            uint32_t aqh[4], aql[4];
            const int qrow = wid * 16 + (lane & 15);
            const int qcol = kb * 16 + (lane >> 4) * 8;
            ldsm4(aqh, cvta_s(&Qh[qrow][qcol]));
            ldsm4(aql, cvta_s(&Ql[qrow][qcol]));
#pragma unroll
            for (int nb = 0; nb < 4; ++nb) {
                const int krow = nb * 16 + (lane & 15);
                uint32_t bh4[4], bl4[4];
                ldsm4(bh4, cvta_s(&Kh[krow][qcol]));
                ldsm4(bl4, cvta_s(&Kl[krow][qcol]));
                uint32_t b0h[2] = {bh4[0], bh4[2]}, b1h[2] = {bh4[1], bh4[3]};
                uint32_t b0l[2] = {bl4[0], bl4[2]}, b1l[2] = {bl4[1], bl4[3]};
                float* s0 = s[nb * 2];
                float* s1 = s[nb * 2 + 1];
                mma_hf(s0, aqh, b0h); mma_hf(s0, aql, b0h); mma_hf(s0, aqh, b0l);
                mma_hf(s1, aqh, b1h); mma_hf(s1, aql, b1h); mma_hf(s1, aqh, b1l);
            }
        }

        float rmax0 = -1e30f, rmax1 = -1e30f;
#pragma unroll
        for (int j = 0; j < 8; ++j) {
            const float bm0 = mb[j * 8 + (lane & 3) * 2];
            const float bm1 = mb[j * 8 + (lane & 3) * 2 + 1];
            s[j][0] += bm0; s[j][1] += bm1; s[j][2] += bm0; s[j][3] += bm1;
            rmax0 = fmaxf(rmax0, fmaxf(s[j][0], s[j][1]));
            rmax1 = fmaxf(rmax1, fmaxf(s[j][2], s[j][3]));
        }
        rmax0 = fmaxf(rmax0, __shfl_xor_sync(0xffffffffu, rmax0, 1));
        rmax0 = fmaxf(rmax0, __shfl_xor_sync(0xffffffffu, rmax0, 2));
        rmax1 = fmaxf(rmax1, __shfl_xor_sync(0xffffffffu, rmax1, 1));
        rmax1 = fmaxf(rmax1, __shfl_xor_sync(0xffffffffu, rmax1, 2));
        const float mn0 = fmaxf(m0, rmax0), mn1 = fmaxf(m1, rmax1);
        const float c0 = ex2((m0 - mn0) * LOG2E), c1 = ex2((m1 - mn1) * LOG2E);
        float rs0 = 0.f, rs1 = 0.f;

        uint32_t pa[4][4];
#pragma unroll
        for (int j2 = 0; j2 < 4; ++j2) {
#pragma unroll
            for (int q = 0; q < 2; ++q) {
                const int j = j2 * 2 + q;
                const float p0 = ex2((s[j][0] - mn0) * LOG2E);
                const float p1 = ex2((s[j][1] - mn0) * LOG2E);
                const float p2 = ex2((s[j][2] - mn1) * LOG2E);
                const float p3 = ex2((s[j][3] - mn1) * LOG2E);
                rs0 += p0 + p1; rs1 += p2 + p3;
                pa[j2][q * 2 + 0] = phf2(p0, p1);
                pa[j2][q * 2 + 1] = phf2(p2, p3);
            }
        }

        rs0 += __shfl_xor_sync(0xffffffffu, rs0, 1);
        rs0 += __shfl_xor_sync(0xffffffffu, rs0, 2);
        rs1 += __shfl_xor_sync(0xffffffffu, rs1, 1);
        rs1 += __shfl_xor_sync(0xffffffffu, rs1, 2);
        l0 = l0 * c0 + rs0; l1 = l1 * c1 + rs1;
        m0 = mn0; m1 = mn1;
#pragma unroll
        for (int j = 0; j < 8; ++j) {
            o[j][0] *= c0; o[j][1] *= c0; o[j][2] *= c1; o[j][3] *= c1;
        }

        const int grp = lane >> 3, li = lane & 7;
#pragma unroll
        for (int j2 = 0; j2 < 4; ++j2) {
            const int vr = j2 * 16 + ((grp & 1) ? 8 : 0) + li;
#pragma unroll
            for (int db = 0; db < 4; ++db) {
                const int vc = db * 16 + ((grp >= 2) ? 8 : 0);
                uint32_t vh4[4];
                ldsm4t(vh4, cvta_s(&Vs[vr][vc]));
                uint32_t b0h[2] = {vh4[0], vh4[1]}, b1h[2] = {vh4[2], vh4[3]};
                mma_hf(o[db * 2],     pa[j2], b0h);
                mma_hf(o[db * 2 + 1], pa[j2], b1h);
            }
        }
    }

    const float inv0 = 1.f / l0, inv1 = 1.f / l1;
    const int r0 = qt * 64 + wid * 16 + (lane >> 2);
#pragma unroll
    for (int db2 = 0; db2 < 8; ++db2) {
        const int d = db2 * 8 + (lane & 3) * 2;
        float2 v0 = make_float2(o[db2][0] * inv0, o[db2][1] * inv0);
        float2 v1 = make_float2(o[db2][2] * inv1, o[db2][3] * inv1);
        *(float2*)(out + (size_t)(b * St + r0) * HIDt + h * 64 + d) = v0;
        *(float2*)(out + (size_t)(b * St + r0 + 8) * HIDt + h * 64 + d) = v1;
    }
}

extern "C" void kernel_launch(void* const* d_in, const int* in_sizes, int n_in,
                              void* d_out, int out_size)
{
    const float* X    = (const float*)d_in[0];
    const float* mask = (const float*)d_in[1];
    const float* Wq   = (const float*)d_in[2];
    const float* bq   = (const float*)d_in[3];
    const float* Wk   = (const float*)d_in[4];
    const float* bk   = (const float*)d_in[5];
    const float* Wv   = (const float*)d_in[6];
    const float* bv   = (const float*)d_in[7];
    float* out = (float*)d_out;

    cudaFuncSetAttribute(qk_gemm, cudaFuncAttributeMaxDynamicSharedMemorySize, QK2_SMEM);
    cudaFuncSetAttribute(v_gemm, cudaFuncAttributeMaxDynamicSharedMemorySize, V_SMEM);
    cudaFuncSetAttribute(attn_mma, cudaFuncAttributeMaxDynamicSharedMemorySize, ASMEM);

    const int total4 = (XN + 3 * WN) / 4;
    split_prep<<<total4 / 256, 256>>>(X, Wq, Wk, Wv);

    dim3 gqk(HIDt / 128, (Bt * St) / 128);
    qk_gemm<<<gqk, 512, QK2_SMEM>>>(bq, bk);

    dim3 gv(HIDt / 128, (Bt * St) / 128);
    v_gemm<<<gv, 256, V_SMEM>>>(bv);

    dim3 g2(St / 64, NHt, Bt);
    attn_mma<<<g2, 128, ASMEM>>>(mask, out);
}

// round 11
// speedup vs baseline: 1.4543x; 1.0017x over previous
#include <cuda_runtime.h>
#include <cuda_fp16.h>
#include <cstdint>

typedef unsigned long long ull;

#define Bt   4
#define St   1024
#define HIDt 1024
#define NHt  16
#define HDt  64
#define LOG2E 1.4426950408889634f
#define NELEM (Bt * NHt * St * HDt)
#define XN (Bt * St * HIDt)
#define WN (HIDt * HIDt)

// fp16 hi/lo split scratch. Q pre-scaled by 0.125. V stored single-fp16.
__device__ __half g_qh[NELEM], g_ql[NELEM];
__device__ __half g_kh[NELEM], g_kl[NELEM];
__device__ __half g_vh[NELEM];
__device__ __half g_xh[XN], g_xl[XN];
__device__ __half g_wh[3 * WN], g_wl[3 * WN];

// ---------------- helpers ----------------
__device__ __forceinline__ uint32_t cvta_s(const void* p) {
    return (uint32_t)__cvta_generic_to_shared(p);
}
__device__ __forceinline__ void ldsm4(uint32_t* r, uint32_t a) {
    asm volatile("ldmatrix.sync.aligned.m8n8.x4.shared.b16 {%0,%1,%2,%3},[%4];"
        : "=r"(r[0]), "=r"(r[1]), "=r"(r[2]), "=r"(r[3]) : "r"(a));
}
__device__ __forceinline__ void ldsm4t(uint32_t* r, uint32_t a) {
    asm volatile("ldmatrix.sync.aligned.m8n8.x4.trans.shared.b16 {%0,%1,%2,%3},[%4];"
        : "=r"(r[0]), "=r"(r[1]), "=r"(r[2]), "=r"(r[3]) : "r"(a));
}
__device__ __forceinline__ void mma_hf(float* c, const uint32_t* a, const uint32_t* b) {
    asm volatile("mma.sync.aligned.m16n8k16.row.col.f32.f16.f16.f32 "
        "{%0,%1,%2,%3},{%4,%5,%6,%7},{%8,%9},{%0,%1,%2,%3};"
        : "+f"(c[0]), "+f"(c[1]), "+f"(c[2]), "+f"(c[3])
        : "r"(a[0]), "r"(a[1]), "r"(a[2]), "r"(a[3]), "r"(b[0]), "r"(b[1]));
}
__device__ __forceinline__ uint32_t phf2(float e0, float e1) {
    uint32_t r; asm("cvt.rn.f16x2.f32 %0, %1, %2;" : "=r"(r) : "f"(e1), "f"(e0)); return r;
}
__device__ __forceinline__ void splith(float x, float& h, float& l) {
    h = __half2float(__float2half(x));
    l = x - h;
}
__device__ __forceinline__ float ex2(float x) {
    float y; asm("ex2.approx.ftz.f32 %0, %1;" : "=f"(y) : "f"(x)); return y;
}
__device__ __forceinline__ void cpa16(uint32_t dst, const void* src) {
    asm volatile("cp.async.cg.shared.global [%0], [%1], 16;" :: "r"(dst), "l"(src));
}
__device__ __forceinline__ void cpa4(uint32_t dst, const void* src) {
    asm volatile("cp.async.ca.shared.global [%0], [%1], 4;" :: "r"(dst), "l"(src));
}
__device__ __forceinline__ void cp_commit() { asm volatile("cp.async.commit_group;"); }
template<int N> __device__ __forceinline__ void cp_wait() {
    asm volatile("cp.async.wait_group %0;" :: "n"(N));
}

// ================= prep: split X / Wq / Wk / Wv to fp16 hi/lo ==============
__global__ __launch_bounds__(256)
void split_prep(const float* __restrict__ X,
                const float* __restrict__ Wq,
                const float* __restrict__ Wk,
                const float* __restrict__ Wv)
{
    const size_t idx = ((size_t)blockIdx.x * 256 + threadIdx.x) * 4;
    const float* src;
    __half *dh, *dl;
    size_t off;
    if (idx < XN)               { src = X;  dh = g_xh; dl = g_xl; off = idx; }
    else if (idx < XN + WN)     { src = Wq; dh = g_wh; dl = g_wl; off = idx - XN; }
    else if (idx < XN + 2 * WN) { src = Wk; dh = g_wh + WN; dl = g_wl + WN; off = idx - XN - WN; }
    else                        { src = Wv; dh = g_wh + 2 * WN; dl = g_wl + 2 * WN; off = idx - XN - 2 * WN; }
    const float4 v = *(const float4*)(src + off);
    float h0, l0, h1, l1, h2, l2, h3, l3;
    splith(v.x, h0, l0); splith(v.y, h1, l1);
    splith(v.z, h2, l2); splith(v.w, h3, l3);
    *(uint2*)(dh + off) = make_uint2(phf2(h0, h1), phf2(h2, h3));
    *(uint2*)(dl + off) = make_uint2(phf2(l0, l1), phf2(l2, l3));
}

// ======== QK fused GEMM: tile 128(M) x 256(N = Q128|K128), 512 threads ======
#define QK_S_AH 0
#define QK_S_AL 24576
#define QK_S_BH 49152
#define QK_S_BL 98304
#define QK2_SMEM 147456

__global__ __launch_bounds__(512, 1)
void qk_gemm(const float* __restrict__ bq, const float* __restrict__ bk)
{
    extern __shared__ __align__(16) char smq[];
    const uint32_t sb = cvta_s(smq);

    const int tid = threadIdx.x;
    const int wid = tid >> 5, lane = tid & 31;
    const int bx = blockIdx.x, by = blockIdx.y;

    const int wm = (wid & 3) * 32;
    const int wn = (wid >> 2) * 64;

    const int rA = tid >> 2, cA = tid & 3;
    const __half* Axh = g_xh + (size_t)(by * 128 + rA) * HIDt;
    const __half* Axl = g_xl + (size_t)(by * 128 + rA) * HIDt;
    const uint32_t swA = (uint32_t)rA * 64 + (((uint32_t)cA ^ ((rA >> 1) & 3)) << 4);

    const int rB = tid >> 1, chp = (tid & 1) * 2;
    const size_t woff = (size_t)(rB >> 7) * WN + (size_t)(bx * 128 + (rB & 127)) * HIDt;
    const __half* Bwh = g_wh + woff;
    const __half* Bwl = g_wl + woff;
    const uint32_t xsB = (rB >> 1) & 3;
    const uint32_t swB0 = (uint32_t)rB * 64 + ((((uint32_t)chp + 0) ^ xsB) << 4);
    const uint32_t swB1 = (uint32_t)rB * 64 + ((((uint32_t)chp + 1) ^ xsB) << 4);

#define QKISSUE(slab, st) do {                                                  \
        const int k0_ = (slab) * 32;                                            \
        cpa16(sb + QK_S_AH + (st) * 8192 + swA, Axh + k0_ + cA * 8);            \
        cpa16(sb + QK_S_AL + (st) * 8192 + swA, Axl + k0_ + cA * 8);            \
        cpa16(sb + QK_S_BH + (st) * 16384 + swB0, Bwh + k0_ + chp * 8);         \
        cpa16(sb + QK_S_BH + (st) * 16384 + swB1, Bwh + k0_ + chp * 8 + 8);     \
        cpa16(sb + QK_S_BL + (st) * 16384 + swB0, Bwl + k0_ + chp * 8);         \
        cpa16(sb + QK_S_BL + (st) * 16384 + swB1, Bwl + k0_ + chp * 8 + 8);     \
        cp_commit();                                                            \
    } while (0)

    float acc[2][8][4];
#pragma unroll
    for (int i = 0; i < 2; ++i)
#pragma unroll
        for (int j = 0; j < 8; ++j)
#pragma unroll
            for (int k = 0; k < 4; ++k) acc[i][j][k] = 0.f;

    uint32_t abase_r[2], xa[2];
#pragma unroll
    for (int mi = 0; mi < 2; ++mi) {
        const int arow = wm + mi * 16 + (lane & 15);
        abase_r[mi] = (uint32_t)arow * 64;
        xa[mi] = (arow >> 1) & 3;
    }
    uint32_t bbase_r[4], xb[4];
#pragma unroll
    for (int nb = 0; nb < 4; ++nb) {
        const int brow = wn + nb * 16 + (lane & 15);
        bbase_r[nb] = (uint32_t)brow * 64;
        xb[nb] = (brow >> 1) & 3;
    }
    const int chalf = lane >> 4;

    QKISSUE(0, 0);
    QKISSUE(1, 1);

    for (int s = 0; s < 32; ++s) {
        const int st = s % 3;
        if (s < 31) cp_wait<1>(); else cp_wait<0>();
        __syncthreads();
        if (s + 2 < 32) QKISSUE(s + 2, (s + 2) % 3);

        const uint32_t ah = sb + QK_S_AH + st * 8192;
        const uint32_t al = sb + QK_S_AL + st * 8192;
        const uint32_t bh = sb + QK_S_BH + st * 16384;
        const uint32_t bl = sb + QK_S_BL + st * 16384;
#pragma unroll
        for (int kb = 0; kb < 2; ++kb) {
            const uint32_t ccol = kb * 2 + chalf;
            uint32_t a_h[2][4], a_l[2][4];
#pragma unroll
            for (int mi = 0; mi < 2; ++mi) {
                const uint32_t aoff = abase_r[mi] + ((ccol ^ xa[mi]) << 4);
                ldsm4(a_h[mi], ah + aoff);
                ldsm4(a_l[mi], al + aoff);
            }
#pragma unroll
            for (int nb = 0; nb < 4; ++nb) {
                const uint32_t boff = bbase_r[nb] + ((ccol ^ xb[nb]) << 4);
                uint32_t bh4[4], bl4[4];
                ldsm4(bh4, bh + boff);
                ldsm4(bl4, bl + boff);
                uint32_t b0h[2] = {bh4[0], bh4[2]}, b1h[2] = {bh4[1], bh4[3]};
                uint32_t b0l[2] = {bl4[0], bl4[2]}, b1l[2] = {bl4[1], bl4[3]};
#pragma unroll
                for (int mi = 0; mi < 2; ++mi) {
                    float* c0 = acc[mi][nb * 2];
                    float* c1 = acc[mi][nb * 2 + 1];
                    mma_hf(c0, a_h[mi], b0h); mma_hf(c0, a_l[mi], b0h); mma_hf(c0, a_h[mi], b0l);
                    mma_hf(c1, a_h[mi], b1h); mma_hf(c1, a_l[mi], b1h); mma_hf(c1, a_h[mi], b1l);
                }
            }
        }
    }
    __syncthreads();

    uint32_t* Cp = (uint32_t*)smq;
    const float* bias = (wn < 128) ? bq : bk;
    const float qs = (wn < 128) ? 0.125f : 1.0f;
#pragma unroll
    for (int mi = 0; mi < 2; ++mi) {
#pragma unroll
        for (int nb2 = 0; nb2 < 8; ++nb2) {
            const int ncol = wn + nb2 * 8 + (lane & 3) * 2;
            const float2 bv2 = *(const float2*)(bias + bx * 128 + (ncol & 127));
            const int colu = ncol >> 1;
#pragma unroll
            for (int rr = 0; rr < 2; ++rr) {
                const int row = wm + mi * 16 + (lane >> 2) + rr * 8;
                const float x0 = (acc[mi][nb2][rr * 2 + 0] + bv2.x) * qs;
                const float x1 = (acc[mi][nb2][rr * 2 + 1] + bv2.y) * qs;
                float h0, l0, h1, l1;
                splith(x0, h0, l0); splith(x1, h1, l1);
                Cp[row * 132 + colu]         = phf2(h0, h1);
                Cp[16896 + row * 132 + colu] = phf2(l0, l1);
            }
        }
    }
    __syncthreads();

#pragma unroll
    for (int it = 0; it < 16; ++it) {
        const int idx = tid + it * 512;
        const int a = idx >> 12;
        const int rem = idx & 4095;
        const int row = rem >> 5;
        const int j = rem & 31;
        const uint32_t sbyte = (uint32_t)a * 67584 + (uint32_t)row * 528 + j * 16;
        const uint4 v = *(const uint4*)(smq + sbyte);
        const int n = j * 8;
        const int ncol = n & 127;
        __half* dst = (n < 128) ? (a ? g_ql : g_qh) : (a ? g_kl : g_kh);
        const int m = by * 128 + row;
        const int bsel = m >> 10, sq = m & 1023;
        const int head = bx * 2 + (ncol >> 6);
        const size_t off = (((size_t)(bsel * NHt + head)) * St + sq) * HDt + (ncol & 63);
        *(uint4*)(dst + off) = v;
    }
#undef QKISSUE
}

// ======== V GEMM: 1-term fp16 (x_h * w_h), tile 128x128, 256 threads =======
#define V_S_AH 0
#define V_S_BH 24576
#define V_SMEM 49152

__global__ __launch_bounds__(256, 2)
void v_gemm(const float* __restrict__ bv)
{
    extern __shared__ __align__(16) char smv[];
    const uint32_t sb = cvta_s(smv);

    const int tid = threadIdx.x;
    const int wid = tid >> 5, lane = tid & 31;
    const int bx = blockIdx.x, by = blockIdx.y;

    const int wm = (wid & 3) * 32;
    const int wn = (wid >> 2) * 64;

    const int r = tid >> 1;
    const int ch = (tid & 1) * 2;
    const __half* Axh = g_xh + (size_t)(by * 128 + r) * HIDt;
    const __half* Bwh = g_wh + 2 * (size_t)WN + (size_t)(bx * 128 + r) * HIDt;
    const uint32_t xs = (r >> 1) & 3;
    const uint32_t sw0 = (uint32_t)r * 64 + ((((uint32_t)ch + 0) ^ xs) << 4);
    const uint32_t sw1 = (uint32_t)r * 64 + ((((uint32_t)ch + 1) ^ xs) << 4);

#define VISSUE(slab, st) do {                                            \
        const int k0_ = (slab) * 32 + ch * 8;                            \
        cpa16(sb + V_S_AH + (st) * 8192 + sw0, Axh + k0_);               \
        cpa16(sb + V_S_AH + (st) * 8192 + sw1, Axh + k0_ + 8);           \
        cpa16(sb + V_S_BH + (st) * 8192 + sw0, Bwh + k0_);               \
        cpa16(sb + V_S_BH + (st) * 8192 + sw1, Bwh + k0_ + 8);           \
        cp_commit();                                                     \
    } while (0)

    float acc[2][8][4];
#pragma unroll
    for (int i = 0; i < 2; ++i)
#pragma unroll
        for (int j = 0; j < 8; ++j)
#pragma unroll
            for (int k = 0; k < 4; ++k) acc[i][j][k] = 0.f;

    uint32_t abase_r[2], xa[2];
#pragma unroll
    for (int mi = 0; mi < 2; ++mi) {
        const int arow = wm + mi * 16 + (lane & 15);
        abase_r[mi] = (uint32_t)arow * 64;
        xa[mi] = (arow >> 1) & 3;
    }
    uint32_t bbase_r[4], xb[4];
#pragma unroll
    for (int nb = 0; nb < 4; ++nb) {
        const int brow = wn + nb * 16 + (lane & 15);
        bbase_r[nb] = (uint32_t)brow * 64;
        xb[nb] = (brow >> 1) & 3;
    }
    const int chalf = lane >> 4;

    VISSUE(0, 0);
    VISSUE(1, 1);

    for (int s = 0; s < 32; ++s) {
        const int st = s % 3;
        if (s < 31) cp_wait<1>(); else cp_wait<0>();
        __syncthreads();
        if (s + 2 < 32) VISSUE(s + 2, (s + 2) % 3);

        const uint32_t ah = sb + V_S_AH + st * 8192;
        const uint32_t bh = sb + V_S_BH + st * 8192;
#pragma unroll
        for (int kb = 0; kb < 2; ++kb) {
            const uint32_t ccol = kb * 2 + chalf;
            uint32_t a_h[2][4];
#pragma unroll
            for (int mi = 0; mi < 2; ++mi) {
                const uint32_t aoff = abase_r[mi] + ((ccol ^ xa[mi]) << 4);
                ldsm4(a_h[mi], ah + aoff);
            }
#pragma unroll
            for (int nb = 0; nb < 4; ++nb) {
                const uint32_t boff = bbase_r[nb] + ((ccol ^ xb[nb]) << 4);
                uint32_t bh4[4];
                ldsm4(bh4, bh + boff);
                uint32_t b0h[2] = {bh4[0], bh4[2]}, b1h[2] = {bh4[1], bh4[3]};
#pragma unroll
                for (int mi = 0; mi < 2; ++mi) {
                    mma_hf(acc[mi][nb * 2],     a_h[mi], b0h);
                    mma_hf(acc[mi][nb * 2 + 1], a_h[mi], b1h);
                }
            }
        }
    }
    __syncthreads();

    uint32_t* Ch = (uint32_t*)smv;
#pragma unroll
    for (int mi = 0; mi < 2; ++mi) {
#pragma unroll
        for (int nb2 = 0; nb2 < 8; ++nb2) {
            const int n = bx * 128 + wn + nb2 * 8 + (lane & 3) * 2;
            const float2 bv2 = *(const float2*)(bv + n);
            const int colu = (wn >> 1) + nb2 * 4 + (lane & 3);
#pragma unroll
            for (int rr = 0; rr < 2; ++rr) {
                const int row = wm + mi * 16 + (lane >> 2) + rr * 8;
                const float x0 = acc[mi][nb2][rr * 2 + 0] + bv2.x;
                const float x1 = acc[mi][nb2][rr * 2 + 1] + bv2.y;
                Ch[row * 68 + colu] = phf2(x0, x1);
            }
        }
    }
    __syncthreads();

#pragma unroll
    for (int it = 0; it < 8; ++it) {
        const int idx = tid + it * 256;
        const int j = idx & 7;
        const int row = (idx >> 3) & 127;
        const int half = (idx >> 10) & 1;
        const uint32_t sbyte = (uint32_t)row * 272 + half * 128 + j * 16;
        const uint4 v = *(const uint4*)(smv + sbyte);
        const int m = by * 128 + row;
        const int bsel = m >> 10, sq = m & 1023;
        const int head = bx * 2 + half;
        const size_t off = (((size_t)(bsel * NHt + head)) * St + sq) * HDt + j * 8;
        *(uint4*)(g_vh + off) = v;
    }
#undef VISSUE
}

// ====== Flash attention (fp16 3-term S, 1-term PV) — cp.async 2-stage KV ====
// smem: Qh 0, Ql 9216; stage st at 18432+st*27648: Kh +0, Kl +9216, Vs +18432;
// raw mask at 73728 + st*256. Total 74240 B.
#define A_STAGE 27648
#define A_KV0   18432
#define A_MB    73728
#define ASMEM   74240

__global__ __launch_bounds__(128)
void attn_mma(const float* __restrict__ mask, float* __restrict__ out)
{
    extern __shared__ __align__(16) char sma[];
    const uint32_t sb = cvta_s(sma);
    __half (*Qh)[72] = (__half(*)[72])(sma);
    __half (*Ql)[72] = (__half(*)[72])(sma + 9216);

    const int tid = threadIdx.x;
    const int lane = tid & 31, wid = tid >> 5;
    const int qt = blockIdx.x, h = blockIdx.y, b = blockIdx.z;

    const size_t bh = ((size_t)(b * NHt + h)) * St * HDt;
    const __half* qhp = g_qh + bh + (size_t)qt * 64 * HDt;
    const __half* qlp = g_ql + bh + (size_t)qt * 64 * HDt;
    const __half* khp = g_kh + bh;
    const __half* klp = g_kl + bh;
    const __half* vhp = g_vh + bh;
    const float* mrow = mask + (size_t)b * St;

#define AISSUE(ktv, stv) do {                                                 \
        const size_t ko_ = (size_t)(ktv) * 64 * HDt;                          \
        const uint32_t base_ = sb + A_KV0 + (stv) * A_STAGE;                  \
        _Pragma("unroll")                                                     \
        for (int j_ = 0; j_ < 4; ++j_) {                                      \
            const int i_ = tid + j_ * 128;                                    \
            const int r_ = i_ >> 3, c_ = (i_ & 7) * 8;                        \
            const uint32_t d_ = base_ + (uint32_t)r_ * 144 + c_ * 2;          \
            cpa16(d_,         khp + ko_ + r_ * 64 + c_);                      \
            cpa16(d_ + 9216,  klp + ko_ + r_ * 64 + c_);                      \
            cpa16(d_ + 18432, vhp + ko_ + r_ * 64 + c_);                      \
        }                                                                     \
        if (tid < 64) cpa4(sb + A_MB + (stv) * 256 + tid * 4,                 \
                           mrow + (ktv) * 64 + tid);                          \
        cp_commit();                                                          \
    } while (0)

    // load Q tile once (plain loads)
    for (int i = tid; i < 512; i += 128) {
        const int r = i >> 3, c = (i & 7) * 8;
        *(uint4*)&Qh[r][c] = *(const uint4*)(qhp + r * 64 + c);
        *(uint4*)&Ql[r][c] = *(const uint4*)(qlp + r * 64 + c);
    }

    AISSUE(0, 0);

    float o[8][4];
#pragma unroll
    for (int j = 0; j < 8; ++j)
#pragma unroll
        for (int k = 0; k < 4; ++k) o[j][k] = 0.f;
    float m0 = -1e30f, m1 = -1e30f, l0 = 0.f, l1 = 0.f;

    for (int kt = 0; kt < 16; ++kt) {
        const int st = kt & 1;
        cp_wait<0>();
        __syncthreads();
        if (kt + 1 < 16) AISSUE(kt + 1, st ^ 1);

        const uint32_t kh = sb + A_KV0 + st * A_STAGE;
        const uint32_t kl = kh + 9216;
        const uint32_t vs = kh + 18432;
        const float* mbs = (const float*)(sma + A_MB + st * 256);

        float s[8][4];
#pragma unroll
        for (int j = 0; j < 8; ++j)
#pragma unroll
            for (int k = 0; k < 4; ++k) s[j][k] = 0.f;

#pragma unroll
        for (int kb = 0; kb < 4; ++kb) {
            uint32_t aqh[4], aql[4];
            const int qrow = wid * 16 + (lane & 15);
            const int qcol = kb * 16 + (lane >> 4) * 8;
            ldsm4(aqh, cvta_s(&Qh[qrow][qcol]));
            ldsm4(aql, cvta_s(&Ql[qrow][qcol]));
#pragma unroll
            for (int nb = 0; nb < 4; ++nb) {
                const int krow = nb * 16 + (lane & 15);
                const uint32_t koff = (uint32_t)krow * 144 + qcol * 2;
                uint32_t bh4[4], bl4[4];
                ldsm4(bh4, kh + koff);
                ldsm4(bl4, kl + koff);
                uint32_t b0h[2] = {bh4[0], bh4[2]}, b1h[2] = {bh4[1], bh4[3]};
                uint32_t b0l[2] = {bl4[0], bl4[2]}, b1l[2] = {bl4[1], bl4[3]};
                float* s0 = s[nb * 2];
                float* s1 = s[nb * 2 + 1];
                mma_hf(s0, aqh, b0h); mma_hf(s0, aql, b0h); mma_hf(s0, aqh, b0l);
                mma_hf(s1, aqh, b1h); mma_hf(s1, aql, b1h); mma_hf(s1, aqh, b1l);
            }
        }

        float rmax0 = -1e30f, rmax1 = -1e30f;
#pragma unroll
        for (int j = 0; j < 8; ++j) {
            const float bm0 = (mbs[j * 8 + (lane & 3) * 2]     - 2.0f) * 1.0e6f;
            const float bm1 = (mbs[j * 8 + (lane & 3) * 2 + 1] - 2.0f) * 1.0e6f;
            s[j][0] += bm0; s[j][1] += bm1; s[j][2] += bm0; s[j][3] += bm1;
            rmax0 = fmaxf(rmax0, fmaxf(s[j][0], s[j][1]));
            rmax1 = fmaxf(rmax1, fmaxf(s[j][2], s[j][3]));
        }
        rmax0 = fmaxf(rmax0, __shfl_xor_sync(0xffffffffu, rmax0, 1));
        rmax0 = fmaxf(rmax0, __shfl_xor_sync(0xffffffffu, rmax0, 2));
        rmax1 = fmaxf(rmax1, __shfl_xor_sync(0xffffffffu, rmax1, 1));
        rmax1 = fmaxf(rmax1, __shfl_xor_sync(0xffffffffu, rmax1, 2));
        const float mn0 = fmaxf(m0, rmax0), mn1 = fmaxf(m1, rmax1);
        const float c0 = ex2((m0 - mn0) * LOG2E), c1 = ex2((m1 - mn1) * LOG2E);
        float rs0 = 0.f, rs1 = 0.f;

        uint32_t pa[4][4];
#pragma unroll
        for (int j2 = 0; j2 < 4; ++j2) {
#pragma unroll
            for (int q = 0; q < 2; ++q) {
                const int j = j2 * 2 + q;
                const float p0 = ex2((s[j][0] - mn0) * LOG2E);
                const float p1 = ex2((s[j][1] - mn0) * LOG2E);
                const float p2 = ex2((s[j][2] - mn1) * LOG2E);
                const float p3 = ex2((s[j][3] - mn1) * LOG2E);
                rs0 += p0 + p1; rs1 += p2 + p3;
                pa[j2][q * 2 + 0] = phf2(p0, p1);
                pa[j2][q * 2 + 1] = phf2(p2, p3);
            }
        }

        rs0 += __shfl_xor_sync(0xffffffffu, rs0, 1);
        rs0 += __shfl_xor_sync(0xffffffffu, rs0, 2);
        rs1 += __shfl_xor_sync(0xffffffffu, rs1, 1);
        rs1 += __shfl_xor_sync(0xffffffffu, rs1, 2);
        l0 = l0 * c0 + rs0; l1 = l1 * c1 + rs1;
        m0 = mn0; m1 = mn1;
#pragma unroll
        for (int j = 0; j < 8; ++j) {
            o[j][0] *= c0; o[j][1] *= c0; o[j][2] *= c1; o[j][3] *= c1;
        }

        const int grp = lane >> 3, li = lane & 7;
#pragma unroll
        for (int j2 = 0; j2 < 4; ++j2) {
            const int vr = j2 * 16 + ((grp & 1) ? 8 : 0) + li;
#pragma unroll
            for (int db = 0; db < 4; ++db) {
                const int vc = db * 16 + ((grp >= 2) ? 8 : 0);
                uint32_t vh4[4];
                ldsm4t(vh4, vs + (uint32_t)vr * 144 + vc * 2);
                uint32_t b0h[2] = {vh4[0], vh4[1]}, b1h[2] = {vh4[2], vh4[3]};
                mma_hf(o[db * 2],     pa[j2], b0h);
                mma_hf(o[db * 2 + 1], pa[j2], b1h);
            }
        }
    }

    const float inv0 = 1.f / l0, inv1 = 1.f / l1;
    const int r0 = qt * 64 + wid * 16 + (lane >> 2);
#pragma unroll
    for (int db2 = 0; db2 < 8; ++db2) {
        const int d = db2 * 8 + (lane & 3) * 2;
        float2 v0 = make_float2(o[db2][0] * inv0, o[db2][1] * inv0);
        float2 v1 = make_float2(o[db2][2] * inv1, o[db2][3] * inv1);
        *(float2*)(out + (size_t)(b * St + r0) * HIDt + h * 64 + d) = v0;
        *(float2*)(out + (size_t)(b * St + r0 + 8) * HIDt + h * 64 + d) = v1;
    }
#undef AISSUE
}

extern "C" void kernel_launch(void* const* d_in, const int* in_sizes, int n_in,
                              void* d_out, int out_size)
{
    const float* X    = (const float*)d_in[0];
    const float* mask = (const float*)d_in[1];
    const float* Wq   = (const float*)d_in[2];
    const float* bq   = (const float*)d_in[3];
    const float* Wk   = (const float*)d_in[4];
    const float* bk   = (const float*)d_in[5];
    const float* Wv   = (const float*)d_in[6];
    const float* bv   = (const float*)d_in[7];
    float* out = (float*)d_out;

    cudaFuncSetAttribute(qk_gemm, cudaFuncAttributeMaxDynamicSharedMemorySize, QK2_SMEM);
    cudaFuncSetAttribute(v_gemm, cudaFuncAttributeMaxDynamicSharedMemorySize, V_SMEM);
    cudaFuncSetAttribute(attn_mma, cudaFuncAttributeMaxDynamicSharedMemorySize, ASMEM);

    const int total4 = (XN + 3 * WN) / 4;
    split_prep<<<total4 / 256, 256>>>(X, Wq, Wk, Wv);

    dim3 gqk(HIDt / 128, (Bt * St) / 128);
    qk_gemm<<<gqk, 512, QK2_SMEM>>>(bq, bk);

    dim3 gv(HIDt / 128, (Bt * St) / 128);
    v_gemm<<<gv, 256, V_SMEM>>>(bv);

    dim3 g2(St / 64, NHt, Bt);
    attn_mma<<<g2, 128, ASMEM>>>(mask, out);
}